// round 6
// baseline (speedup 1.0000x reference)
#include <cuda_runtime.h>
#include <math.h>

#define N_NODES  100000
#define N_EDGES  3200000
#define N_GRAPHS 512
#define HID      256
#define MIDC     128
#define OUTC     16
#define LN_EPS   1e-5f

// ---------------- scratch (device globals: no allocation allowed) ------------
// 16-byte alignment REQUIRED on float4-accessed arrays.
__device__ __align__(16) float  g_h[(size_t)N_NODES * HID];
__device__ __align__(16) float  g_agg[(size_t)N_NODES * HID];
__device__ float  g_deg[N_NODES];
__device__ float  g_dinv[N_NODES];
__device__ double g_red[2];                       // sum, sumsq
__device__ __align__(16) float  g_pooled[N_GRAPHS * HID];
__device__ float  g_cnt[N_GRAPHS];
__device__ float  g_mid[N_GRAPHS * MIDC];
// int32 staging for indices (input may be int32 or int64 -- detected at runtime)
__device__ int    g_flag;                         // 1 = int32 input, 0 = int64
__device__ int    g_src[N_EDGES];
__device__ int    g_dst[N_EDGES];
__device__ int    g_batch[N_NODES];

// ---------------- helpers ----------------------------------------------------
__device__ __forceinline__ void red_add_v4(float4* p, float x, float y, float z, float w) {
    asm volatile("red.global.add.v4.f32 [%0], {%1,%2,%3,%4};"
                 :: "l"(p), "f"(x), "f"(y), "f"(z), "f"(w) : "memory");
}

__device__ __forceinline__ int clampi(int v, int hi) {
    return v < 0 ? 0 : (v >= hi ? hi - 1 : v);
}

// ---------------- dtype detect + convert -------------------------------------
__global__ void k_zero_misc() {
    if (blockIdx.x == 0 && threadIdx.x == 0) { g_flag = 0; g_red[0] = 0.0; g_red[1] = 0.0; }
    int i = blockIdx.x * blockDim.x + threadIdx.x;
    if (i < N_NODES) g_deg[i] = 0.0f;
    if (i < N_GRAPHS * HID) g_pooled[i] = 0.0f;
    if (i < N_GRAPHS) g_cnt[i] = 0.0f;
}

// Sample odd 32-bit words of the first half of the edge buffer (always in
// bounds for both dtypes). int64 little-endian values < 2^31 have zero high
// words at odd positions; int32 has real node ids there (some of 4096 samples
// certainly nonzero).
__global__ void k_detect(const unsigned int* __restrict__ w) {
    int t = blockIdx.x * blockDim.x + threadIdx.x;     // 4096 threads
    long long idx = (long long)t * ((long long)N_EDGES / 4096);  // < N_EDGES
    if (w[idx | 1] != 0u) atomicOr(&g_flag, 1);
}

__global__ void k_cvt_edges(const void* __restrict__ ei) {
    int e = blockIdx.x * blockDim.x + threadIdx.x;
    if (e >= N_EDGES) return;
    int s, d;
    if (g_flag) {
        const int* p = (const int*)ei;
        s = p[e]; d = p[N_EDGES + e];
    } else {
        const long long* p = (const long long*)ei;
        s = (int)p[e]; d = (int)p[N_EDGES + e];
    }
    g_src[e] = clampi(s, N_NODES);
    g_dst[e] = clampi(d, N_NODES);
}

__global__ void k_cvt_batch(const void* __restrict__ b) {
    int i = blockIdx.x * blockDim.x + threadIdx.x;
    if (i >= N_NODES) return;
    int v = g_flag ? ((const int*)b)[i] : (int)((const long long*)b)[i];
    g_batch[i] = clampi(v, N_GRAPHS);
}

// ---------------- graph preprocessing ----------------------------------------
__global__ void k_deg() {
    int e = blockIdx.x * blockDim.x + threadIdx.x;
    if (e < N_EDGES) atomicAdd(&g_deg[g_dst[e]], 1.0f);
}

__global__ void k_dinv() {
    int i = blockIdx.x * blockDim.x + threadIdx.x;
    if (i < N_NODES) g_dinv[i] = rsqrtf(g_deg[i] + 1.0f);   // +1: self loop
}

// ---------------- layer kernels ----------------------------------------------
// h = pos @ W1 (IN_C=2); fused: agg = bias + h*dinv^2 (self loop)
__global__ void k_in_gemm(const float* __restrict__ pos, const float* __restrict__ w,
                          const float* __restrict__ bias) {
    int n = blockIdx.x, c = threadIdx.x;
    float p0 = pos[2 * n], p1 = pos[2 * n + 1];
    float h = p0 * w[c] + p1 * w[HID + c];
    float d = g_dinv[n];
    g_h[(size_t)n * HID + c]   = h;
    g_agg[(size_t)n * HID + c] = bias[c] + h * d * d;
}

// warp per edge: agg[dst] += h[src] * (dinv[src]*dinv[dst])
__global__ void k_agg_edges() {
    int t = blockIdx.x * blockDim.x + threadIdx.x;
    int e = t >> 5;
    if (e >= N_EDGES) return;
    int lane = threadIdx.x & 31;
    int s = g_src[e], d = g_dst[e];
    float nrm = g_dinv[s] * g_dinv[d];
    const float4* hs = (const float4*)(g_h + (size_t)s * HID);
    float4* ad = (float4*)(g_agg + (size_t)d * HID);
    float4 v0 = hs[lane];
    float4 v1 = hs[lane + 32];
    red_add_v4(ad + lane,      v0.x * nrm, v0.y * nrm, v0.z * nrm, v0.w * nrm);
    red_add_v4(ad + lane + 32, v1.x * nrm, v1.y * nrm, v1.z * nrm, v1.w * nrm);
}

__global__ void k_zero_red() { g_red[0] = 0.0; g_red[1] = 0.0; }

// sum / sumsq of g_agg
__global__ void k_reduce() {
    const int n = N_NODES * HID;
    float s = 0.0f, s2 = 0.0f;
    int stride = gridDim.x * blockDim.x;
    for (int i = blockIdx.x * blockDim.x + threadIdx.x; i < n; i += stride) {
        float v = g_agg[i];
        s += v; s2 += v * v;
    }
    for (int o = 16; o > 0; o >>= 1) {
        s  += __shfl_xor_sync(0xffffffffu, s,  o);
        s2 += __shfl_xor_sync(0xffffffffu, s2, o);
    }
    __shared__ float sh[2][8];
    int w = threadIdx.x >> 5, l = threadIdx.x & 31;
    if (l == 0) { sh[0][w] = s; sh[1][w] = s2; }
    __syncthreads();
    if (threadIdx.x == 0) {
        float ts = 0.0f, ts2 = 0.0f;
        #pragma unroll
        for (int i = 0; i < 8; i++) { ts += sh[0][i]; ts2 += sh[1][i]; }
        atomicAdd(&g_red[0], (double)ts);
        atomicAdd(&g_red[1], (double)ts2);
    }
}

// in-place graph LN + PReLU
__global__ void k_ln_apply(const float* __restrict__ w, const float* __restrict__ b,
                           const float* __restrict__ alpha) {
    const int n = N_NODES * HID;
    int i = blockIdx.x * blockDim.x + threadIdx.x;
    if (i >= n) return;
    double mean_d = g_red[0] / (double)n;
    double var_d  = g_red[1] / (double)n - mean_d * mean_d;
    float mean = (float)mean_d;
    float inv  = 1.0f / (sqrtf(fmaxf((float)var_d, 0.0f)) + LN_EPS);
    int c = i & (HID - 1);
    float v = (g_agg[i] - mean) * inv * w[c] + b[c];
    float a = *alpha;
    g_agg[i] = (v >= 0.0f) ? v : a * v;
}

// g_h = g_agg (M x 256) @ W (256 x 256). Tiled SGEMM.
__global__ void k_gemm(const float* __restrict__ W) {
    const int BM = 64, BN = 64, BK = 16, K = 256, N = 256, M = N_NODES;
    __shared__ float As[BK][BM + 4];
    __shared__ float Bs[BK][BN];
    int bm = blockIdx.x * BM, bn = blockIdx.y * BN;
    int tx = threadIdx.x;
    int trow = tx >> 4, tcol = tx & 15;
    float acc[4][4] = {};
    for (int k0 = 0; k0 < K; k0 += BK) {
        #pragma unroll
        for (int i = tx; i < BM * BK; i += 256) {
            int m = i / BK, kk = i % BK;
            int gr = bm + m;
            As[kk][m] = (gr < M) ? g_agg[(size_t)gr * K + k0 + kk] : 0.0f;
        }
        #pragma unroll
        for (int i = tx; i < BK * BN; i += 256) {
            int kk = i / BN, nn = i % BN;
            Bs[kk][nn] = W[(size_t)(k0 + kk) * N + bn + nn];
        }
        __syncthreads();
        #pragma unroll
        for (int kk = 0; kk < BK; kk++) {
            float a0 = As[kk][trow * 4 + 0], a1 = As[kk][trow * 4 + 1];
            float a2 = As[kk][trow * 4 + 2], a3 = As[kk][trow * 4 + 3];
            float b0 = Bs[kk][tcol * 4 + 0], b1 = Bs[kk][tcol * 4 + 1];
            float b2 = Bs[kk][tcol * 4 + 2], b3 = Bs[kk][tcol * 4 + 3];
            acc[0][0] += a0 * b0; acc[0][1] += a0 * b1; acc[0][2] += a0 * b2; acc[0][3] += a0 * b3;
            acc[1][0] += a1 * b0; acc[1][1] += a1 * b1; acc[1][2] += a1 * b2; acc[1][3] += a1 * b3;
            acc[2][0] += a2 * b0; acc[2][1] += a2 * b1; acc[2][2] += a2 * b2; acc[2][3] += a2 * b3;
            acc[3][0] += a3 * b0; acc[3][1] += a3 * b1; acc[3][2] += a3 * b2; acc[3][3] += a3 * b3;
        }
        __syncthreads();
    }
    #pragma unroll
    for (int r = 0; r < 4; r++) {
        int gr = bm + trow * 4 + r;
        if (gr < M) {
            #pragma unroll
            for (int c = 0; c < 4; c++)
                g_h[(size_t)gr * N + bn + tcol * 4 + c] = acc[r][c];
        }
    }
}

// agg = bias + h * dinv^2  (layer 2 seed; g_agg was GEMM input so separate pass)
__global__ void k_agg_init(const float* __restrict__ bias) {
    int n = blockIdx.x, c = threadIdx.x;
    float d = g_dinv[n];
    g_agg[(size_t)n * HID + c] = bias[c] + g_h[(size_t)n * HID + c] * d * d;
}

// ---------------- pooling + MLP ----------------------------------------------
__global__ void k_pool() {
    int t = blockIdx.x * blockDim.x + threadIdx.x;
    int n = t >> 5;
    if (n >= N_NODES) return;
    int lane = threadIdx.x & 31;
    int b = g_batch[n];
    const float4* x = (const float4*)(g_agg + (size_t)n * HID);
    float4* p = (float4*)(g_pooled + (size_t)b * HID);
    float4 v0 = x[lane];
    float4 v1 = x[lane + 32];
    red_add_v4(p + lane,      v0.x, v0.y, v0.z, v0.w);
    red_add_v4(p + lane + 32, v1.x, v1.y, v1.z, v1.w);
    if (lane == 0) atomicAdd(&g_cnt[b], 1.0f);
}

__global__ void k_pool_div() {
    int i = blockIdx.x * blockDim.x + threadIdx.x;   // 512*256
    g_pooled[i] /= fmaxf(g_cnt[i >> 8], 1.0f);
}

__global__ void k_lin1(const float* __restrict__ W, const float* __restrict__ bias) {
    int t = blockIdx.x * blockDim.x + threadIdx.x;   // 512*128
    int g = t >> 7, j = t & 127;
    const float* row = g_pooled + (size_t)g * HID;
    float s = 0.0f;
    #pragma unroll 8
    for (int c = 0; c < HID; c++) s += row[c] * W[(size_t)c * MIDC + j];
    g_mid[t] = s + bias[j];
}

__global__ void k_ln_mid(const float* __restrict__ w, const float* __restrict__ b,
                         const float* __restrict__ alpha) {
    const int n = N_GRAPHS * MIDC;
    float a = *alpha;
    float s = 0.0f, s2 = 0.0f;
    for (int i = threadIdx.x; i < n; i += blockDim.x) {
        float v = g_mid[i]; s += v; s2 += v * v;
    }
    for (int o = 16; o > 0; o >>= 1) {
        s  += __shfl_xor_sync(0xffffffffu, s,  o);
        s2 += __shfl_xor_sync(0xffffffffu, s2, o);
    }
    __shared__ float sh[2][32];
    __shared__ float mstd[2];
    int wr = threadIdx.x >> 5, l = threadIdx.x & 31;
    if (l == 0) { sh[0][wr] = s; sh[1][wr] = s2; }
    __syncthreads();
    if (threadIdx.x == 0) {
        float ts = 0.0f, ts2 = 0.0f;
        int nw = blockDim.x >> 5;
        for (int i = 0; i < nw; i++) { ts += sh[0][i]; ts2 += sh[1][i]; }
        float mean = ts / n;
        float var  = ts2 / n - mean * mean;
        mstd[0] = mean;
        mstd[1] = 1.0f / (sqrtf(fmaxf(var, 0.0f)) + LN_EPS);
    }
    __syncthreads();
    float mean = mstd[0], inv = mstd[1];
    for (int i = threadIdx.x; i < n; i += blockDim.x) {
        int c = i & (MIDC - 1);
        float v = (g_mid[i] - mean) * inv * w[c] + b[c];
        g_mid[i] = (v >= 0.0f) ? v : a * v;
    }
}

__global__ void k_lin2(const float* __restrict__ W, const float* __restrict__ bias,
                       float* __restrict__ out) {
    int t = blockIdx.x * blockDim.x + threadIdx.x;   // 512*16
    int g = t >> 4, o = t & 15;
    const float* row = g_mid + (size_t)g * MIDC;
    float s = 0.0f;
    #pragma unroll 8
    for (int j = 0; j < MIDC; j++) s += row[j] * W[(size_t)j * OUTC + o];
    out[t] = s + bias[o];
}

// ---------------- launch -----------------------------------------------------
extern "C" void kernel_launch(void* const* d_in, const int* in_sizes, int n_in,
                              void* d_out, int out_size) {
    const float* pos    = (const float*)d_in[0];
    const void*  ei     = d_in[1];
    const void*  batch  = d_in[2];
    const float* w_conv1 = (const float*)d_in[3];
    const float* b_conv1 = (const float*)d_in[4];
    const float* ln1_w   = (const float*)d_in[5];
    const float* ln1_b   = (const float*)d_in[6];
    const float* a1      = (const float*)d_in[7];
    const float* w_conv2 = (const float*)d_in[8];
    const float* b_conv2 = (const float*)d_in[9];
    const float* ln2_w   = (const float*)d_in[10];
    const float* ln2_b   = (const float*)d_in[11];
    const float* a2      = (const float*)d_in[12];
    const float* w_lin1  = (const float*)d_in[13];
    const float* b_lin1  = (const float*)d_in[14];
    const float* lnm_w   = (const float*)d_in[15];
    const float* lnm_b   = (const float*)d_in[16];
    const float* am      = (const float*)d_in[17];
    const float* w_lin2  = (const float*)d_in[18];
    const float* b_lin2  = (const float*)d_in[19];
    float* out = (float*)d_out;

    // init + dtype detect + index conversion
    k_zero_misc<<<(N_GRAPHS * HID + 255) / 256, 256>>>();
    k_detect<<<16, 256>>>((const unsigned int*)ei);
    k_cvt_edges<<<(N_EDGES + 255) / 256, 256>>>(ei);
    k_cvt_batch<<<(N_NODES + 255) / 256, 256>>>(batch);

    // degree / normalization
    k_deg<<<(N_EDGES + 255) / 256, 256>>>();
    k_dinv<<<(N_NODES + 255) / 256, 256>>>();

    // ----- layer 1 -----
    k_in_gemm<<<N_NODES, HID>>>(pos, w_conv1, b_conv1);
    k_agg_edges<<<(N_EDGES * 32) / 256, 256>>>();
    k_reduce<<<2048, 256>>>();
    k_ln_apply<<<(N_NODES * HID) / 256, 256>>>(ln1_w, ln1_b, a1);

    // ----- layer 2 -----
    k_gemm<<<dim3((N_NODES + 63) / 64, 4), 256>>>(w_conv2);
    k_agg_init<<<N_NODES, HID>>>(b_conv2);
    k_agg_edges<<<(N_EDGES * 32) / 256, 256>>>();
    k_zero_red<<<1, 1>>>();
    k_reduce<<<2048, 256>>>();
    k_ln_apply<<<(N_NODES * HID) / 256, 256>>>(ln2_w, ln2_b, a2);

    // ----- pooling + MLP -----
    k_pool<<<(N_NODES * 32 + 255) / 256, 256>>>();
    k_pool_div<<<(N_GRAPHS * HID) / 256, 256>>>();
    k_lin1<<<(N_GRAPHS * MIDC) / 256, 256>>>(w_lin1, b_lin1);
    k_ln_mid<<<1, 1024>>>(lnm_w, lnm_b, am);
    k_lin2<<<(N_GRAPHS * OUTC) / 256, 256>>>(w_lin2, b_lin2, out);
}

// round 7
// speedup vs baseline: 2.4995x; 2.4995x over previous
#include <cuda_runtime.h>
#include <math.h>

#define N_NODES  100000
#define N_EDGES  3200000
#define N_GRAPHS 512
#define HID      256
#define MIDC     128
#define OUTC     16
#define LN_EPS   1e-5f
#define NBLK     391                    // ceil(N_NODES/256)

// ---------------- scratch (device globals) -----------------------------------
__device__ __align__(16) float  g_x[(size_t)N_NODES * HID];    // layer-1 output
__device__ __align__(16) float  g_h[(size_t)N_NODES * HID];    // gemm output
__device__ __align__(16) float  g_agg[(size_t)N_NODES * HID];  // layer-2 agg
__device__ float  g_dinv[N_NODES];
__device__ int    g_degi[N_NODES];
__device__ int    g_cur[N_NODES];
__device__ int    g_off[N_NODES + 1];
__device__ int    g_bsum[NBLK];
__device__ int    g_boff[NBLK];
__device__ int2   g_edge[N_EDGES];            // (src, nrm bits) sorted by dst
__device__ float  g_A[2 * N_NODES];           // rank-2 aggregate (layer 1)
__device__ double g_mA[5];                    // SA0,SA1,S00,S11,S01
__device__ float  g_stats1[2];                // mean, inv  (layer 1 LN)
__device__ double g_red[2];                   // sum, sumsq (layer 2 LN)
__device__ float  g_stats2[2];
__device__ __align__(16) float  g_pooled[N_GRAPHS * HID];
__device__ float  g_cnt[N_GRAPHS];
__device__ float  g_mid[N_GRAPHS * MIDC];
__device__ int    g_flag;                     // 1 = int32 input, 0 = int64
__device__ int    g_src[N_EDGES];
__device__ int    g_dst[N_EDGES];
__device__ int    g_batch[N_NODES];

// ---------------- helpers ----------------------------------------------------
__device__ __forceinline__ void red_add_v4(float4* p, float x, float y, float z, float w) {
    asm volatile("red.global.add.v4.f32 [%0], {%1,%2,%3,%4};"
                 :: "l"(p), "f"(x), "f"(y), "f"(z), "f"(w) : "memory");
}
__device__ __forceinline__ int clampi(int v, int hi) {
    return v < 0 ? 0 : (v >= hi ? hi - 1 : v);
}

// ---------------- init / dtype / conversion ----------------------------------
__global__ void k_init() {
    int i = blockIdx.x * blockDim.x + threadIdx.x;        // 200704 threads
    if (i == 0) { g_flag = 0; g_red[0] = 0.0; g_red[1] = 0.0;
                  for (int k = 0; k < 5; k++) g_mA[k] = 0.0; }
    if (i < N_NODES) { g_degi[i] = 0; g_cur[i] = 0; }
    if (i < 2 * N_NODES) g_A[i] = 0.0f;
    if (i < N_GRAPHS * HID) g_pooled[i] = 0.0f;
    if (i < N_GRAPHS) g_cnt[i] = 0.0f;
}

__global__ void k_detect(const unsigned int* __restrict__ w) {
    int t = blockIdx.x * blockDim.x + threadIdx.x;         // 4096 threads
    long long idx = (long long)t * ((long long)N_EDGES / 4096);
    if (w[idx | 1] != 0u) atomicOr(&g_flag, 1);
}

__global__ void k_cvt_edges(const void* __restrict__ ei) {
    int e = blockIdx.x * blockDim.x + threadIdx.x;
    if (e >= N_EDGES) return;
    int s, d;
    if (g_flag) {
        const int* p = (const int*)ei;
        s = p[e]; d = p[N_EDGES + e];
    } else {
        const long long* p = (const long long*)ei;
        s = (int)p[e]; d = (int)p[N_EDGES + e];
    }
    g_src[e] = clampi(s, N_NODES);
    g_dst[e] = clampi(d, N_NODES);
}

__global__ void k_cvt_batch(const void* __restrict__ b) {
    int i = blockIdx.x * blockDim.x + threadIdx.x;
    if (i >= N_NODES) return;
    int v = g_flag ? ((const int*)b)[i] : (int)((const long long*)b)[i];
    g_batch[i] = clampi(v, N_GRAPHS);
}

// ---------------- CSR build ---------------------------------------------------
__global__ void k_hist() {
    int e = blockIdx.x * blockDim.x + threadIdx.x;
    if (e < N_EDGES) atomicAdd(&g_degi[g_dst[e]], 1);
}

__global__ void k_dinv() {
    int i = blockIdx.x * blockDim.x + threadIdx.x;
    if (i < N_NODES) g_dinv[i] = rsqrtf((float)g_degi[i] + 1.0f);
}

__global__ void k_scan_block() {
    __shared__ int sh[256];
    int t = threadIdx.x, i = blockIdx.x * 256 + t;
    int v = (i < N_NODES) ? g_degi[i] : 0;
    sh[t] = v; __syncthreads();
    for (int o = 1; o < 256; o <<= 1) {
        int x = (t >= o) ? sh[t - o] : 0;
        __syncthreads(); sh[t] += x; __syncthreads();
    }
    if (i < N_NODES) g_off[i] = sh[t] - v;                 // exclusive-in-block
    if (t == 255) g_bsum[blockIdx.x] = sh[255];
}

__global__ void k_scan_top() {
    __shared__ int sh[512];
    int t = threadIdx.x;
    int v = (t < NBLK) ? g_bsum[t] : 0;
    sh[t] = v; __syncthreads();
    for (int o = 1; o < 512; o <<= 1) {
        int x = (t >= o) ? sh[t - o] : 0;
        __syncthreads(); sh[t] += x; __syncthreads();
    }
    if (t < NBLK) g_boff[t] = sh[t] - v;                   // exclusive
}

__global__ void k_scan_add() {
    int i = blockIdx.x * blockDim.x + threadIdx.x;
    if (i < N_NODES) g_off[i] += g_boff[i >> 8];
    if (i == 0) g_off[N_NODES] = N_EDGES;
}

// scatter edges by dst; fused rank-2 aggregation of pos for layer 1
__global__ void k_scatter(const float* __restrict__ pos) {
    int e = blockIdx.x * blockDim.x + threadIdx.x;
    if (e >= N_EDGES) return;
    int s = g_src[e], d = g_dst[e];
    float nrm = g_dinv[s] * g_dinv[d];
    int p = g_off[d] + atomicAdd(&g_cur[d], 1);
    g_edge[p] = make_int2(s, __float_as_int(nrm));
    atomicAdd(&g_A[2 * d + 0], nrm * pos[2 * s]);
    atomicAdd(&g_A[2 * d + 1], nrm * pos[2 * s + 1]);
}

__global__ void k_selfq(const float* __restrict__ pos) {
    int n = blockIdx.x * blockDim.x + threadIdx.x;
    if (n >= N_NODES) return;
    float d = g_dinv[n], d2 = d * d;
    g_A[2 * n + 0] += d2 * pos[2 * n];
    g_A[2 * n + 1] += d2 * pos[2 * n + 1];
}

// ---------------- layer 1: analytic LN stats + fused expand -------------------
__global__ void k_moments() {
    int n = blockIdx.x * blockDim.x + threadIdx.x;
    float a0 = 0.f, a1 = 0.f;
    if (n < N_NODES) { a0 = g_A[2 * n]; a1 = g_A[2 * n + 1]; }
    float p0 = a0, p1 = a1, p2 = a0 * a0, p3 = a1 * a1, p4 = a0 * a1;
    __shared__ float sh[5][256];
    int t = threadIdx.x;
    sh[0][t] = p0; sh[1][t] = p1; sh[2][t] = p2; sh[3][t] = p3; sh[4][t] = p4;
    __syncthreads();
    for (int o = 128; o > 0; o >>= 1) {
        if (t < o)
            for (int k = 0; k < 5; k++) sh[k][t] += sh[k][t + o];
        __syncthreads();
    }
    if (t == 0)
        for (int k = 0; k < 5; k++) atomicAdd(&g_mA[k], (double)sh[k][0]);
}

__global__ void k_stats1(const float* __restrict__ w, const float* __restrict__ b) {
    __shared__ double sh[9][256];
    int c = threadIdx.x;
    double w0 = w[c], w1 = w[c + HID], bc = b[c];
    sh[0][c] = bc;        sh[1][c] = bc * bc;
    sh[2][c] = w0;        sh[3][c] = w1;
    sh[4][c] = w0 * w0;   sh[5][c] = w1 * w1;
    sh[6][c] = w0 * w1;   sh[7][c] = bc * w0;   sh[8][c] = bc * w1;
    __syncthreads();
    for (int o = 128; o > 0; o >>= 1) {
        if (c < o)
            for (int k = 0; k < 9; k++) sh[k][c] += sh[k][c + o];
        __syncthreads();
    }
    if (c == 0) {
        double Sb = sh[0][0], Sb2 = sh[1][0], SW0 = sh[2][0], SW1 = sh[3][0];
        double SW0q = sh[4][0], SW1q = sh[5][0], SW01 = sh[6][0];
        double SbW0 = sh[7][0], SbW1 = sh[8][0];
        double SA0 = g_mA[0], SA1 = g_mA[1], S00 = g_mA[2], S11 = g_mA[3], S01 = g_mA[4];
        double Nn = (double)N_NODES, NC = Nn * (double)HID;
        double sum = Nn * Sb + SA0 * SW0 + SA1 * SW1;
        double ss  = Nn * Sb2 + S00 * SW0q + S11 * SW1q
                   + 2.0 * (SA0 * SbW0 + SA1 * SbW1 + S01 * SW01);
        double mean = sum / NC;
        double var  = ss / NC - mean * mean;
        g_stats1[0] = (float)mean;
        g_stats1[1] = 1.0f / ((float)sqrt(var > 0.0 ? var : 0.0) + LN_EPS);
    }
}

// x1 = prelu(LN(b + A0*W0 + A1*W1))   -- one write pass, no intermediates
__global__ void k_expand(const float* __restrict__ w, const float* __restrict__ b,
                         const float* __restrict__ lnw, const float* __restrict__ lnb,
                         const float* __restrict__ alpha) {
    int n = blockIdx.x, c = threadIdx.x;
    float A0 = g_A[2 * n], A1 = g_A[2 * n + 1];
    float pre = b[c] + A0 * w[c] + A1 * w[c + HID];
    float v = (pre - g_stats1[0]) * g_stats1[1] * lnw[c] + lnb[c];
    float a = *alpha;
    g_x[(size_t)n * HID + c] = (v >= 0.0f) ? v : a * v;
}

// ---------------- layer 2 -----------------------------------------------------
// g_h = g_x (M x 256) @ W (256 x 256). Tiled SGEMM.
__global__ void k_gemm(const float* __restrict__ W) {
    const int BM = 64, BN = 64, BK = 16, K = 256, N = 256, M = N_NODES;
    __shared__ float As[BK][BM + 4];
    __shared__ float Bs[BK][BN];
    int bm = blockIdx.x * BM, bn = blockIdx.y * BN;
    int tx = threadIdx.x;
    int trow = tx >> 4, tcol = tx & 15;
    float acc[4][4] = {};
    for (int k0 = 0; k0 < K; k0 += BK) {
        #pragma unroll
        for (int i = tx; i < BM * BK; i += 256) {
            int m = i / BK, kk = i % BK;
            int gr = bm + m;
            As[kk][m] = (gr < M) ? g_x[(size_t)gr * K + k0 + kk] : 0.0f;
        }
        #pragma unroll
        for (int i = tx; i < BK * BN; i += 256) {
            int kk = i / BN, nn = i % BN;
            Bs[kk][nn] = W[(size_t)(k0 + kk) * N + bn + nn];
        }
        __syncthreads();
        #pragma unroll
        for (int kk = 0; kk < BK; kk++) {
            float a0 = As[kk][trow * 4 + 0], a1 = As[kk][trow * 4 + 1];
            float a2 = As[kk][trow * 4 + 2], a3 = As[kk][trow * 4 + 3];
            float b0 = Bs[kk][tcol * 4 + 0], b1 = Bs[kk][tcol * 4 + 1];
            float b2 = Bs[kk][tcol * 4 + 2], b3 = Bs[kk][tcol * 4 + 3];
            acc[0][0] += a0 * b0; acc[0][1] += a0 * b1; acc[0][2] += a0 * b2; acc[0][3] += a0 * b3;
            acc[1][0] += a1 * b0; acc[1][1] += a1 * b1; acc[1][2] += a1 * b2; acc[1][3] += a1 * b3;
            acc[2][0] += a2 * b0; acc[2][1] += a2 * b1; acc[2][2] += a2 * b2; acc[2][3] += a2 * b3;
            acc[3][0] += a3 * b0; acc[3][1] += a3 * b1; acc[3][2] += a3 * b2; acc[3][3] += a3 * b3;
        }
        __syncthreads();
    }
    #pragma unroll
    for (int r = 0; r < 4; r++) {
        int gr = bm + trow * 4 + r;
        if (gr < M) {
            #pragma unroll
            for (int c = 0; c < 4; c++)
                g_h[(size_t)gr * N + bn + tcol * 4 + c] = acc[r][c];
        }
    }
}

// warp-per-node CSR aggregation + bias + self loop; block epilogue: LN stats
__global__ void k_agg2(const float* __restrict__ bias) {
    int t = blockIdx.x * blockDim.x + threadIdx.x;
    int n = t >> 5;                                // 12500 blocks x 8 warps exact
    int lane = t & 31;
    const float4* bi = (const float4*)bias;
    float4 acc0 = bi[lane];
    float4 acc1 = bi[lane + 32];
    {
        const float4* hr = (const float4*)(g_h + (size_t)n * HID);
        float d = g_dinv[n], d2 = d * d;
        float4 h0 = hr[lane], h1 = hr[lane + 32];
        acc0.x += d2 * h0.x; acc0.y += d2 * h0.y; acc0.z += d2 * h0.z; acc0.w += d2 * h0.w;
        acc1.x += d2 * h1.x; acc1.y += d2 * h1.y; acc1.z += d2 * h1.z; acc1.w += d2 * h1.w;
    }
    int e = g_off[n], e1 = g_off[n + 1];
    for (; e + 1 < e1; e += 2) {
        int2 ea = g_edge[e], eb = g_edge[e + 1];
        float fa = __int_as_float(ea.y), fb = __int_as_float(eb.y);
        const float4* ha = (const float4*)(g_h + (size_t)ea.x * HID);
        const float4* hb = (const float4*)(g_h + (size_t)eb.x * HID);
        float4 a0 = ha[lane], a1 = ha[lane + 32];
        float4 b0 = hb[lane], b1 = hb[lane + 32];
        acc0.x += fa * a0.x + fb * b0.x; acc0.y += fa * a0.y + fb * b0.y;
        acc0.z += fa * a0.z + fb * b0.z; acc0.w += fa * a0.w + fb * b0.w;
        acc1.x += fa * a1.x + fb * b1.x; acc1.y += fa * a1.y + fb * b1.y;
        acc1.z += fa * a1.z + fb * b1.z; acc1.w += fa * a1.w + fb * b1.w;
    }
    if (e < e1) {
        int2 ea = g_edge[e];
        float fa = __int_as_float(ea.y);
        const float4* ha = (const float4*)(g_h + (size_t)ea.x * HID);
        float4 a0 = ha[lane], a1 = ha[lane + 32];
        acc0.x += fa * a0.x; acc0.y += fa * a0.y; acc0.z += fa * a0.z; acc0.w += fa * a0.w;
        acc1.x += fa * a1.x; acc1.y += fa * a1.y; acc1.z += fa * a1.z; acc1.w += fa * a1.w;
    }
    float4* out = (float4*)(g_agg + (size_t)n * HID);
    out[lane] = acc0;
    out[lane + 32] = acc1;
    // LN stats epilogue
    float s  = acc0.x + acc0.y + acc0.z + acc0.w + acc1.x + acc1.y + acc1.z + acc1.w;
    float s2 = acc0.x * acc0.x + acc0.y * acc0.y + acc0.z * acc0.z + acc0.w * acc0.w
             + acc1.x * acc1.x + acc1.y * acc1.y + acc1.z * acc1.z + acc1.w * acc1.w;
    for (int o = 16; o > 0; o >>= 1) {
        s  += __shfl_xor_sync(0xffffffffu, s,  o);
        s2 += __shfl_xor_sync(0xffffffffu, s2, o);
    }
    __shared__ float sh[2][8];
    int w = threadIdx.x >> 5;
    if (lane == 0) { sh[0][w] = s; sh[1][w] = s2; }
    __syncthreads();
    if (threadIdx.x == 0) {
        float ts = 0.f, ts2 = 0.f;
        #pragma unroll
        for (int i = 0; i < 8; i++) { ts += sh[0][i]; ts2 += sh[1][i]; }
        atomicAdd(&g_red[0], (double)ts);
        atomicAdd(&g_red[1], (double)ts2);
    }
}

__global__ void k_stats2() {
    double NC = (double)N_NODES * (double)HID;
    double mean = g_red[0] / NC;
    double var  = g_red[1] / NC - mean * mean;
    g_stats2[0] = (float)mean;
    g_stats2[1] = 1.0f / ((float)sqrt(var > 0.0 ? var : 0.0) + LN_EPS);
}

// fused LN2 + PReLU + mean-pool scatter (x2 never materialized)
__global__ void k_pool_ln(const float* __restrict__ lnw, const float* __restrict__ lnb,
                          const float* __restrict__ alpha) {
    int t = blockIdx.x * blockDim.x + threadIdx.x;
    int n = t >> 5;
    if (n >= N_NODES) return;
    int lane = t & 31;
    float mean = g_stats2[0], inv = g_stats2[1], a = *alpha;
    const float4* x = (const float4*)(g_agg + (size_t)n * HID);
    const float4* w4 = (const float4*)lnw;
    const float4* b4 = (const float4*)lnb;
    float4* p = (float4*)(g_pooled + (size_t)g_batch[n] * HID);
    float4 v0 = x[lane], v1 = x[lane + 32];
    float4 w0 = w4[lane], w1 = w4[lane + 32];
    float4 c0 = b4[lane], c1 = b4[lane + 32];
    float r[8];
    r[0] = (v0.x - mean) * inv * w0.x + c0.x;
    r[1] = (v0.y - mean) * inv * w0.y + c0.y;
    r[2] = (v0.z - mean) * inv * w0.z + c0.z;
    r[3] = (v0.w - mean) * inv * w0.w + c0.w;
    r[4] = (v1.x - mean) * inv * w1.x + c1.x;
    r[5] = (v1.y - mean) * inv * w1.y + c1.y;
    r[6] = (v1.z - mean) * inv * w1.z + c1.z;
    r[7] = (v1.w - mean) * inv * w1.w + c1.w;
    #pragma unroll
    for (int i = 0; i < 8; i++) r[i] = (r[i] >= 0.0f) ? r[i] : a * r[i];
    red_add_v4(p + lane,      r[0], r[1], r[2], r[3]);
    red_add_v4(p + lane + 32, r[4], r[5], r[6], r[7]);
    if (lane == 0) atomicAdd(&g_cnt[g_batch[n]], 1.0f);
}

// ---------------- pooled MLP --------------------------------------------------
__global__ void k_pool_div() {
    int i = blockIdx.x * blockDim.x + threadIdx.x;   // 512*256
    g_pooled[i] /= fmaxf(g_cnt[i >> 8], 1.0f);
}

__global__ void k_lin1(const float* __restrict__ W, const float* __restrict__ bias) {
    int t = blockIdx.x * blockDim.x + threadIdx.x;   // 512*128
    int g = t >> 7, j = t & 127;
    const float* row = g_pooled + (size_t)g * HID;
    float s = 0.0f;
    #pragma unroll 8
    for (int c = 0; c < HID; c++) s += row[c] * W[(size_t)c * MIDC + j];
    g_mid[t] = s + bias[j];
}

__global__ void k_ln_mid(const float* __restrict__ w, const float* __restrict__ b,
                         const float* __restrict__ alpha) {
    const int n = N_GRAPHS * MIDC;
    float a = *alpha;
    float s = 0.0f, s2 = 0.0f;
    for (int i = threadIdx.x; i < n; i += blockDim.x) {
        float v = g_mid[i]; s += v; s2 += v * v;
    }
    for (int o = 16; o > 0; o >>= 1) {
        s  += __shfl_xor_sync(0xffffffffu, s,  o);
        s2 += __shfl_xor_sync(0xffffffffu, s2, o);
    }
    __shared__ float sh[2][32];
    __shared__ float mstd[2];
    int wr = threadIdx.x >> 5, l = threadIdx.x & 31;
    if (l == 0) { sh[0][wr] = s; sh[1][wr] = s2; }
    __syncthreads();
    if (threadIdx.x == 0) {
        float ts = 0.0f, ts2 = 0.0f;
        int nw = blockDim.x >> 5;
        for (int i = 0; i < nw; i++) { ts += sh[0][i]; ts2 += sh[1][i]; }
        float mean = ts / n;
        float var  = ts2 / n - mean * mean;
        mstd[0] = mean;
        mstd[1] = 1.0f / (sqrtf(fmaxf(var, 0.0f)) + LN_EPS);
    }
    __syncthreads();
    float mean = mstd[0], inv = mstd[1];
    for (int i = threadIdx.x; i < n; i += blockDim.x) {
        int c = i & (MIDC - 1);
        float v = (g_mid[i] - mean) * inv * w[c] + b[c];
        g_mid[i] = (v >= 0.0f) ? v : a * v;
    }
}

__global__ void k_lin2(const float* __restrict__ W, const float* __restrict__ bias,
                       float* __restrict__ out) {
    int t = blockIdx.x * blockDim.x + threadIdx.x;   // 512*16
    int g = t >> 4, o = t & 15;
    const float* row = g_mid + (size_t)g * MIDC;
    float s = 0.0f;
    #pragma unroll 8
    for (int j = 0; j < MIDC; j++) s += row[j] * W[(size_t)j * OUTC + o];
    out[t] = s + bias[o];
}

// ---------------- launch -----------------------------------------------------
extern "C" void kernel_launch(void* const* d_in, const int* in_sizes, int n_in,
                              void* d_out, int out_size) {
    const float* pos    = (const float*)d_in[0];
    const void*  ei     = d_in[1];
    const void*  batch  = d_in[2];
    const float* w_conv1 = (const float*)d_in[3];
    const float* b_conv1 = (const float*)d_in[4];
    const float* ln1_w   = (const float*)d_in[5];
    const float* ln1_b   = (const float*)d_in[6];
    const float* a1      = (const float*)d_in[7];
    const float* w_conv2 = (const float*)d_in[8];
    const float* b_conv2 = (const float*)d_in[9];
    const float* ln2_w   = (const float*)d_in[10];
    const float* ln2_b   = (const float*)d_in[11];
    const float* a2      = (const float*)d_in[12];
    const float* w_lin1  = (const float*)d_in[13];
    const float* b_lin1  = (const float*)d_in[14];
    const float* lnm_w   = (const float*)d_in[15];
    const float* lnm_b   = (const float*)d_in[16];
    const float* am      = (const float*)d_in[17];
    const float* w_lin2  = (const float*)d_in[18];
    const float* b_lin2  = (const float*)d_in[19];
    float* out = (float*)d_out;

    // init + dtype detect + index conversion
    k_init<<<(2 * N_NODES + 255) / 256, 256>>>();
    k_detect<<<16, 256>>>((const unsigned int*)ei);
    k_cvt_edges<<<(N_EDGES + 255) / 256, 256>>>(ei);
    k_cvt_batch<<<(N_NODES + 255) / 256, 256>>>(batch);

    // CSR build (+ fused rank-2 layer-1 aggregation in scatter)
    k_hist<<<(N_EDGES + 255) / 256, 256>>>();
    k_dinv<<<(N_NODES + 255) / 256, 256>>>();
    k_scan_block<<<NBLK, 256>>>();
    k_scan_top<<<1, 512>>>();
    k_scan_add<<<NBLK, 256>>>();
    k_scatter<<<(N_EDGES + 255) / 256, 256>>>(pos);
    k_selfq<<<(N_NODES + 255) / 256, 256>>>(pos);

    // layer 1: analytic LN + fused expand
    k_moments<<<NBLK, 256>>>();
    k_stats1<<<1, 256>>>(w_conv1, b_conv1);
    k_expand<<<N_NODES, 256>>>(w_conv1, b_conv1, ln1_w, ln1_b, a1);

    // layer 2
    k_gemm<<<dim3((N_NODES + 63) / 64, 4), 256>>>(w_conv2);
    k_agg2<<<(N_NODES * 32) / 256, 256>>>(b_conv2);
    k_stats2<<<1, 1>>>();

    // fused LN2 + PReLU + pooling, then MLP
    k_pool_ln<<<(N_NODES * 32 + 255) / 256, 256>>>(ln2_w, ln2_b, a2);
    k_pool_div<<<(N_GRAPHS * HID) / 256, 256>>>();
    k_lin1<<<(N_GRAPHS * MIDC) / 256, 256>>>(w_lin1, b_lin1);
    k_ln_mid<<<1, 1024>>>(lnm_w, lnm_b, am);
    k_lin2<<<(N_GRAPHS * OUTC) / 256, 256>>>(w_lin2, b_lin2, out);
}

// round 8
// speedup vs baseline: 3.8431x; 1.5376x over previous
#include <cuda_runtime.h>
#include <cuda_fp16.h>
#include <math.h>
#include <stdint.h>

#define N_NODES  100000
#define N_EDGES  3200000
#define N_GRAPHS 512
#define HID      256
#define MIDC     128
#define OUTC     16
#define LN_EPS   1e-5f
#define NBLK     391                    // ceil(N_NODES/256)

// ---------------- scratch (device globals) -----------------------------------
__device__ __align__(16) float  g_x[(size_t)N_NODES * HID];    // layer-1 output
__device__ __align__(16) __half g_hh[(size_t)N_NODES * HID];   // gemm output (fp16)
__device__ __align__(16) float  g_agg[(size_t)N_NODES * HID];  // layer-2 agg
__device__ float  g_dinv[N_NODES];
__device__ int    g_degi[N_NODES];
__device__ int    g_cur[N_NODES];
__device__ int    g_off[N_NODES + 1];
__device__ int    g_bsum[NBLK];
__device__ int    g_boff[NBLK];
__device__ int2   g_edge[N_EDGES];            // (src, nrm bits) sorted by dst
__device__ float  g_A[2 * N_NODES];           // rank-2 aggregate (layer 1)
__device__ double g_mA[5];                    // SA0,SA1,S00,S11,S01
__device__ float  g_stats1[2];                // mean, inv  (layer 1 LN)
__device__ double g_red[2];                   // sum, sumsq (layer 2 LN)
__device__ float  g_stats2[2];
__device__ __align__(16) float  g_pooled[N_GRAPHS * HID];
__device__ float  g_cnt[N_GRAPHS];
__device__ float  g_mid[N_GRAPHS * MIDC];
__device__ int    g_flag;                     // 1 = int32 input, 0 = int64
__device__ int    g_src[N_EDGES];
__device__ int    g_dst[N_EDGES];
__device__ int    g_batch[N_NODES];

// ---------------- helpers ----------------------------------------------------
__device__ __forceinline__ void red_add_v4(float4* p, float x, float y, float z, float w) {
    asm volatile("red.global.add.v4.f32 [%0], {%1,%2,%3,%4};"
                 :: "l"(p), "f"(x), "f"(y), "f"(z), "f"(w) : "memory");
}
__device__ __forceinline__ int clampi(int v, int hi) {
    return v < 0 ? 0 : (v >= hi ? hi - 1 : v);
}
__device__ __forceinline__ uint32_t f2tf32(float f) {
    uint32_t u;
    asm("cvt.rna.tf32.f32 %0, %1;" : "=r"(u) : "f"(f));
    return u;
}
__device__ __forceinline__ void mma_tf32(float* c, const uint32_t* a, const uint32_t* b) {
    asm("mma.sync.aligned.m16n8k8.row.col.f32.tf32.tf32.f32 "
        "{%0,%1,%2,%3}, {%4,%5,%6,%7}, {%8,%9}, {%0,%1,%2,%3};"
        : "+f"(c[0]), "+f"(c[1]), "+f"(c[2]), "+f"(c[3])
        : "r"(a[0]), "r"(a[1]), "r"(a[2]), "r"(a[3]), "r"(b[0]), "r"(b[1]));
}

// ---------------- init / dtype / conversion ----------------------------------
__global__ void k_init() {
    int i = blockIdx.x * blockDim.x + threadIdx.x;
    if (i == 0) { g_flag = 0; g_red[0] = 0.0; g_red[1] = 0.0;
                  for (int k = 0; k < 5; k++) g_mA[k] = 0.0; }
    if (i < N_NODES) { g_degi[i] = 0; g_cur[i] = 0; }
    if (i < 2 * N_NODES) g_A[i] = 0.0f;
    if (i < N_GRAPHS * HID) g_pooled[i] = 0.0f;
    if (i < N_GRAPHS) g_cnt[i] = 0.0f;
}

__global__ void k_detect(const unsigned int* __restrict__ w) {
    int t = blockIdx.x * blockDim.x + threadIdx.x;         // 4096 threads
    long long idx = (long long)t * ((long long)N_EDGES / 4096);
    if (w[idx | 1] != 0u) atomicOr(&g_flag, 1);
}

// convert indices + degree histogram fused
__global__ void k_cvt_edges(const void* __restrict__ ei) {
    int e = blockIdx.x * blockDim.x + threadIdx.x;
    if (e >= N_EDGES) return;
    int s, d;
    if (g_flag) {
        const int* p = (const int*)ei;
        s = p[e]; d = p[N_EDGES + e];
    } else {
        const long long* p = (const long long*)ei;
        s = (int)p[e]; d = (int)p[N_EDGES + e];
    }
    s = clampi(s, N_NODES); d = clampi(d, N_NODES);
    g_src[e] = s;
    g_dst[e] = d;
    atomicAdd(&g_degi[d], 1);
}

__global__ void k_cvt_batch(const void* __restrict__ b) {
    int i = blockIdx.x * blockDim.x + threadIdx.x;
    if (i >= N_NODES) return;
    int v = g_flag ? ((const int*)b)[i] : (int)((const long long*)b)[i];
    g_batch[i] = clampi(v, N_GRAPHS);
}

// ---------------- CSR build ---------------------------------------------------
__global__ void k_dinv() {
    int i = blockIdx.x * blockDim.x + threadIdx.x;
    if (i < N_NODES) g_dinv[i] = rsqrtf((float)g_degi[i] + 1.0f);
}

__global__ void k_scan_block() {
    __shared__ int sh[256];
    int t = threadIdx.x, i = blockIdx.x * 256 + t;
    int v = (i < N_NODES) ? g_degi[i] : 0;
    sh[t] = v; __syncthreads();
    for (int o = 1; o < 256; o <<= 1) {
        int x = (t >= o) ? sh[t - o] : 0;
        __syncthreads(); sh[t] += x; __syncthreads();
    }
    if (i < N_NODES) g_off[i] = sh[t] - v;
    if (t == 255) g_bsum[blockIdx.x] = sh[255];
}

__global__ void k_scan_top() {
    __shared__ int sh[512];
    int t = threadIdx.x;
    int v = (t < NBLK) ? g_bsum[t] : 0;
    sh[t] = v; __syncthreads();
    for (int o = 1; o < 512; o <<= 1) {
        int x = (t >= o) ? sh[t - o] : 0;
        __syncthreads(); sh[t] += x; __syncthreads();
    }
    if (t < NBLK) g_boff[t] = sh[t] - v;
}

__global__ void k_scan_add() {
    int i = blockIdx.x * blockDim.x + threadIdx.x;
    if (i < N_NODES) g_off[i] += g_boff[i >> 8];
    if (i == 0) g_off[N_NODES] = N_EDGES;
}

// scatter edges by dst; fused rank-2 aggregation of pos for layer 1
__global__ void k_scatter(const float* __restrict__ pos) {
    int e = blockIdx.x * blockDim.x + threadIdx.x;
    if (e >= N_EDGES) return;
    int s = g_src[e], d = g_dst[e];
    float nrm = g_dinv[s] * g_dinv[d];
    int p = g_off[d] + atomicAdd(&g_cur[d], 1);
    g_edge[p] = make_int2(s, __float_as_int(nrm));
    atomicAdd(&g_A[2 * d + 0], nrm * pos[2 * s]);
    atomicAdd(&g_A[2 * d + 1], nrm * pos[2 * s + 1]);
}

// self-loop term + node-moment reduction (fused)
__global__ void k_selfq(const float* __restrict__ pos) {
    int n = blockIdx.x * blockDim.x + threadIdx.x;
    float a0 = 0.f, a1 = 0.f;
    if (n < N_NODES) {
        float d = g_dinv[n], d2 = d * d;
        a0 = g_A[2 * n + 0] + d2 * pos[2 * n];
        a1 = g_A[2 * n + 1] + d2 * pos[2 * n + 1];
        g_A[2 * n + 0] = a0;
        g_A[2 * n + 1] = a1;
    }
    __shared__ float sh[5][256];
    int t = threadIdx.x;
    sh[0][t] = a0; sh[1][t] = a1; sh[2][t] = a0 * a0; sh[3][t] = a1 * a1; sh[4][t] = a0 * a1;
    __syncthreads();
    for (int o = 128; o > 0; o >>= 1) {
        if (t < o)
            for (int k = 0; k < 5; k++) sh[k][t] += sh[k][t + o];
        __syncthreads();
    }
    if (t == 0)
        for (int k = 0; k < 5; k++) atomicAdd(&g_mA[k], (double)sh[k][0]);
}

// ---------------- layer 1: analytic LN stats + fused expand -------------------
__global__ void k_stats1(const float* __restrict__ w, const float* __restrict__ b) {
    __shared__ double sh[9][256];
    int c = threadIdx.x;
    double w0 = w[c], w1 = w[c + HID], bc = b[c];
    sh[0][c] = bc;        sh[1][c] = bc * bc;
    sh[2][c] = w0;        sh[3][c] = w1;
    sh[4][c] = w0 * w0;   sh[5][c] = w1 * w1;
    sh[6][c] = w0 * w1;   sh[7][c] = bc * w0;   sh[8][c] = bc * w1;
    __syncthreads();
    for (int o = 128; o > 0; o >>= 1) {
        if (c < o)
            for (int k = 0; k < 9; k++) sh[k][c] += sh[k][c + o];
        __syncthreads();
    }
    if (c == 0) {
        double Sb = sh[0][0], Sb2 = sh[1][0], SW0 = sh[2][0], SW1 = sh[3][0];
        double SW0q = sh[4][0], SW1q = sh[5][0], SW01 = sh[6][0];
        double SbW0 = sh[7][0], SbW1 = sh[8][0];
        double SA0 = g_mA[0], SA1 = g_mA[1], S00 = g_mA[2], S11 = g_mA[3], S01 = g_mA[4];
        double Nn = (double)N_NODES, NC = Nn * (double)HID;
        double sum = Nn * Sb + SA0 * SW0 + SA1 * SW1;
        double ss  = Nn * Sb2 + S00 * SW0q + S11 * SW1q
                   + 2.0 * (SA0 * SbW0 + SA1 * SbW1 + S01 * SW01);
        double mean = sum / NC;
        double var  = ss / NC - mean * mean;
        g_stats1[0] = (float)mean;
        g_stats1[1] = 1.0f / ((float)sqrt(var > 0.0 ? var : 0.0) + LN_EPS);
    }
}

// x1 = prelu(LN(b + A0*W0 + A1*W1))
__global__ void k_expand(const float* __restrict__ w, const float* __restrict__ b,
                         const float* __restrict__ lnw, const float* __restrict__ lnb,
                         const float* __restrict__ alpha) {
    int n = blockIdx.x, c = threadIdx.x;
    float A0 = g_A[2 * n], A1 = g_A[2 * n + 1];
    float pre = b[c] + A0 * w[c] + A1 * w[c + HID];
    float v = (pre - g_stats1[0]) * g_stats1[1] * lnw[c] + lnb[c];
    float a = *alpha;
    g_x[(size_t)n * HID + c] = (v >= 0.0f) ? v : a * v;
}

// ---------------- layer 2: tf32 tensor-core GEMM ------------------------------
// g_hh = (half) g_x (M x 256) @ W (256 x 256). Block tile 128x64, 8 warps 32x32.
__global__ void k_gemm(const float* __restrict__ W) {
    __shared__ uint32_t As[128][17];
    __shared__ uint32_t Bs[16][65];
    const int M = N_NODES;
    int t = threadIdx.x;
    int lane = t & 31, warp = t >> 5;
    int wr = warp >> 1, wc = warp & 1;
    int g = lane >> 2, tig = lane & 3;
    int bm = blockIdx.x * 128, bn = blockIdx.y * 64;

    float c[2][4][4];
    #pragma unroll
    for (int i = 0; i < 2; i++)
        #pragma unroll
        for (int j = 0; j < 4; j++)
            #pragma unroll
            for (int r = 0; r < 4; r++) c[i][j][r] = 0.0f;

    int am = t >> 1, akb = (t & 1) * 8;     // A staging: row, k-offset
    int bkk = t >> 4, bc4 = (t & 15) * 4;   // B staging

    for (int k0 = 0; k0 < 256; k0 += 16) {
        // stage A (tf32-converted)
        int gr = bm + am;
        float4 v0 = make_float4(0.f, 0.f, 0.f, 0.f), v1 = v0;
        if (gr < M) {
            const float4* p = (const float4*)(g_x + (size_t)gr * 256 + k0 + akb);
            v0 = p[0]; v1 = p[1];
        }
        As[am][akb + 0] = f2tf32(v0.x); As[am][akb + 1] = f2tf32(v0.y);
        As[am][akb + 2] = f2tf32(v0.z); As[am][akb + 3] = f2tf32(v0.w);
        As[am][akb + 4] = f2tf32(v1.x); As[am][akb + 5] = f2tf32(v1.y);
        As[am][akb + 6] = f2tf32(v1.z); As[am][akb + 7] = f2tf32(v1.w);
        // stage B
        {
            const float4* p = (const float4*)(W + (size_t)(k0 + bkk) * 256 + bn + bc4);
            float4 wv = p[0];
            Bs[bkk][bc4 + 0] = f2tf32(wv.x); Bs[bkk][bc4 + 1] = f2tf32(wv.y);
            Bs[bkk][bc4 + 2] = f2tf32(wv.z); Bs[bkk][bc4 + 3] = f2tf32(wv.w);
        }
        __syncthreads();
        #pragma unroll
        for (int kk = 0; kk < 16; kk += 8) {
            uint32_t a[2][4], b[4][2];
            #pragma unroll
            for (int i = 0; i < 2; i++) {
                int r0 = wr * 32 + i * 16 + g;
                a[i][0] = As[r0][kk + tig];
                a[i][1] = As[r0 + 8][kk + tig];
                a[i][2] = As[r0][kk + tig + 4];
                a[i][3] = As[r0 + 8][kk + tig + 4];
            }
            #pragma unroll
            for (int j = 0; j < 4; j++) {
                int cb = wc * 32 + j * 8 + g;
                b[j][0] = Bs[kk + tig][cb];
                b[j][1] = Bs[kk + tig + 4][cb];
            }
            #pragma unroll
            for (int i = 0; i < 2; i++)
                #pragma unroll
                for (int j = 0; j < 4; j++)
                    mma_tf32(c[i][j], a[i], b[j]);
        }
        __syncthreads();
    }
    // epilogue: write fp16
    #pragma unroll
    for (int i = 0; i < 2; i++) {
        int r0 = bm + wr * 32 + i * 16 + g;
        int r1 = r0 + 8;
        #pragma unroll
        for (int j = 0; j < 4; j++) {
            int col = bn + wc * 32 + j * 8 + 2 * tig;
            if (r0 < M)
                *(__half2*)(g_hh + (size_t)r0 * 256 + col) = __floats2half2_rn(c[i][j][0], c[i][j][1]);
            if (r1 < M)
                *(__half2*)(g_hh + (size_t)r1 * 256 + col) = __floats2half2_rn(c[i][j][2], c[i][j][3]);
        }
    }
}

// warp-per-node CSR aggregation (fp16 gather, fp32 accum) + LN stats epilogue
__global__ void k_agg2(const float* __restrict__ bias) {
    int t = blockIdx.x * blockDim.x + threadIdx.x;
    int n = t >> 5;
    int lane = t & 31;
    float acc[8];
    {   // bias (channels lane*8 .. lane*8+7)
        const float4* b4 = (const float4*)(bias + lane * 8);
        float4 x = b4[0], y = b4[1];
        acc[0] = x.x; acc[1] = x.y; acc[2] = x.z; acc[3] = x.w;
        acc[4] = y.x; acc[5] = y.y; acc[6] = y.z; acc[7] = y.w;
    }
    {   // self loop
        float d = g_dinv[n], d2 = d * d;
        int4 v = ((const int4*)(g_hh + (size_t)n * HID))[lane];
        const __half2* h = (const __half2*)&v;
        #pragma unroll
        for (int i = 0; i < 4; i++) {
            float2 f = __half22float2(h[i]);
            acc[2 * i]     += d2 * f.x;
            acc[2 * i + 1] += d2 * f.y;
        }
    }
    int e = g_off[n], e1 = g_off[n + 1];
    for (; e + 1 < e1; e += 2) {
        int2 ea = g_edge[e], eb = g_edge[e + 1];
        float fa = __int_as_float(ea.y), fb = __int_as_float(eb.y);
        int4 va = ((const int4*)(g_hh + (size_t)ea.x * HID))[lane];
        int4 vb = ((const int4*)(g_hh + (size_t)eb.x * HID))[lane];
        const __half2* ha = (const __half2*)&va;
        const __half2* hb = (const __half2*)&vb;
        #pragma unroll
        for (int i = 0; i < 4; i++) {
            float2 xa = __half22float2(ha[i]);
            float2 xb = __half22float2(hb[i]);
            acc[2 * i]     += fa * xa.x + fb * xb.x;
            acc[2 * i + 1] += fa * xa.y + fb * xb.y;
        }
    }
    if (e < e1) {
        int2 ea = g_edge[e];
        float fa = __int_as_float(ea.y);
        int4 va = ((const int4*)(g_hh + (size_t)ea.x * HID))[lane];
        const __half2* ha = (const __half2*)&va;
        #pragma unroll
        for (int i = 0; i < 4; i++) {
            float2 xa = __half22float2(ha[i]);
            acc[2 * i]     += fa * xa.x;
            acc[2 * i + 1] += fa * xa.y;
        }
    }
    float4* out = (float4*)(g_agg + (size_t)n * HID);
    out[lane * 2]     = make_float4(acc[0], acc[1], acc[2], acc[3]);
    out[lane * 2 + 1] = make_float4(acc[4], acc[5], acc[6], acc[7]);
    // LN stats epilogue
    float s = 0.f, s2 = 0.f;
    #pragma unroll
    for (int i = 0; i < 8; i++) { s += acc[i]; s2 += acc[i] * acc[i]; }
    for (int o = 16; o > 0; o >>= 1) {
        s  += __shfl_xor_sync(0xffffffffu, s,  o);
        s2 += __shfl_xor_sync(0xffffffffu, s2, o);
    }
    __shared__ float sh[2][8];
    int w = threadIdx.x >> 5;
    if (lane == 0) { sh[0][w] = s; sh[1][w] = s2; }
    __syncthreads();
    if (threadIdx.x == 0) {
        float ts = 0.f, ts2 = 0.f;
        #pragma unroll
        for (int i = 0; i < 8; i++) { ts += sh[0][i]; ts2 += sh[1][i]; }
        atomicAdd(&g_red[0], (double)ts);
        atomicAdd(&g_red[1], (double)ts2);
    }
}

__global__ void k_stats2() {
    double NC = (double)N_NODES * (double)HID;
    double mean = g_red[0] / NC;
    double var  = g_red[1] / NC - mean * mean;
    g_stats2[0] = (float)mean;
    g_stats2[1] = 1.0f / ((float)sqrt(var > 0.0 ? var : 0.0) + LN_EPS);
}

// fused LN2 + PReLU + mean-pool scatter
__global__ void k_pool_ln(const float* __restrict__ lnw, const float* __restrict__ lnb,
                          const float* __restrict__ alpha) {
    int t = blockIdx.x * blockDim.x + threadIdx.x;
    int n = t >> 5;
    if (n >= N_NODES) return;
    int lane = t & 31;
    float mean = g_stats2[0], inv = g_stats2[1], a = *alpha;
    const float4* x = (const float4*)(g_agg + (size_t)n * HID);
    const float4* w4 = (const float4*)lnw;
    const float4* b4 = (const float4*)lnb;
    float4* p = (float4*)(g_pooled + (size_t)g_batch[n] * HID);
    float4 v0 = x[lane], v1 = x[lane + 32];
    float4 w0 = w4[lane], w1 = w4[lane + 32];
    float4 c0 = b4[lane], c1 = b4[lane + 32];
    float r[8];
    r[0] = (v0.x - mean) * inv * w0.x + c0.x;
    r[1] = (v0.y - mean) * inv * w0.y + c0.y;
    r[2] = (v0.z - mean) * inv * w0.z + c0.z;
    r[3] = (v0.w - mean) * inv * w0.w + c0.w;
    r[4] = (v1.x - mean) * inv * w1.x + c1.x;
    r[5] = (v1.y - mean) * inv * w1.y + c1.y;
    r[6] = (v1.z - mean) * inv * w1.z + c1.z;
    r[7] = (v1.w - mean) * inv * w1.w + c1.w;
    #pragma unroll
    for (int i = 0; i < 8; i++) r[i] = (r[i] >= 0.0f) ? r[i] : a * r[i];
    red_add_v4(p + lane,      r[0], r[1], r[2], r[3]);
    red_add_v4(p + lane + 32, r[4], r[5], r[6], r[7]);
    if (lane == 0) atomicAdd(&g_cnt[g_batch[n]], 1.0f);
}

// ---------------- pooled MLP --------------------------------------------------
__global__ void k_pool_div() {
    int i = blockIdx.x * blockDim.x + threadIdx.x;
    g_pooled[i] /= fmaxf(g_cnt[i >> 8], 1.0f);
}

__global__ void k_lin1(const float* __restrict__ W, const float* __restrict__ bias) {
    int t = blockIdx.x * blockDim.x + threadIdx.x;
    int g = t >> 7, j = t & 127;
    const float* row = g_pooled + (size_t)g * HID;
    float s = 0.0f;
    #pragma unroll 8
    for (int c = 0; c < HID; c++) s += row[c] * W[(size_t)c * MIDC + j];
    g_mid[t] = s + bias[j];
}

__global__ void k_ln_mid(const float* __restrict__ w, const float* __restrict__ b,
                         const float* __restrict__ alpha) {
    const int n = N_GRAPHS * MIDC;
    float a = *alpha;
    float s = 0.0f, s2 = 0.0f;
    for (int i = threadIdx.x; i < n; i += blockDim.x) {
        float v = g_mid[i]; s += v; s2 += v * v;
    }
    for (int o = 16; o > 0; o >>= 1) {
        s  += __shfl_xor_sync(0xffffffffu, s,  o);
        s2 += __shfl_xor_sync(0xffffffffu, s2, o);
    }
    __shared__ float sh[2][32];
    __shared__ float mstd[2];
    int wr = threadIdx.x >> 5, l = threadIdx.x & 31;
    if (l == 0) { sh[0][wr] = s; sh[1][wr] = s2; }
    __syncthreads();
    if (threadIdx.x == 0) {
        float ts = 0.0f, ts2 = 0.0f;
        int nw = blockDim.x >> 5;
        for (int i = 0; i < nw; i++) { ts += sh[0][i]; ts2 += sh[1][i]; }
        float mean = ts / n;
        float var  = ts2 / n - mean * mean;
        mstd[0] = mean;
        mstd[1] = 1.0f / (sqrtf(fmaxf(var, 0.0f)) + LN_EPS);
    }
    __syncthreads();
    float mean = mstd[0], inv = mstd[1];
    for (int i = threadIdx.x; i < n; i += blockDim.x) {
        int c = i & (MIDC - 1);
        float v = (g_mid[i] - mean) * inv * w[c] + b[c];
        g_mid[i] = (v >= 0.0f) ? v : a * v;
    }
}

__global__ void k_lin2(const float* __restrict__ W, const float* __restrict__ bias,
                       float* __restrict__ out) {
    int t = blockIdx.x * blockDim.x + threadIdx.x;
    int g = t >> 4, o = t & 15;
    const float* row = g_mid + (size_t)g * MIDC;
    float s = 0.0f;
    #pragma unroll 8
    for (int j = 0; j < MIDC; j++) s += row[j] * W[(size_t)j * OUTC + o];
    out[t] = s + bias[o];
}

// ---------------- launch -----------------------------------------------------
extern "C" void kernel_launch(void* const* d_in, const int* in_sizes, int n_in,
                              void* d_out, int out_size) {
    const float* pos    = (const float*)d_in[0];
    const void*  ei     = d_in[1];
    const void*  batch  = d_in[2];
    const float* w_conv1 = (const float*)d_in[3];
    const float* b_conv1 = (const float*)d_in[4];
    const float* ln1_w   = (const float*)d_in[5];
    const float* ln1_b   = (const float*)d_in[6];
    const float* a1      = (const float*)d_in[7];
    const float* w_conv2 = (const float*)d_in[8];
    const float* b_conv2 = (const float*)d_in[9];
    const float* ln2_w   = (const float*)d_in[10];
    const float* ln2_b   = (const float*)d_in[11];
    const float* a2      = (const float*)d_in[12];
    const float* w_lin1  = (const float*)d_in[13];
    const float* b_lin1  = (const float*)d_in[14];
    const float* lnm_w   = (const float*)d_in[15];
    const float* lnm_b   = (const float*)d_in[16];
    const float* am      = (const float*)d_in[17];
    const float* w_lin2  = (const float*)d_in[18];
    const float* b_lin2  = (const float*)d_in[19];
    float* out = (float*)d_out;

    // init + dtype detect + index conversion (+degree hist fused)
    k_init<<<(2 * N_NODES + 255) / 256, 256>>>();
    k_detect<<<16, 256>>>((const unsigned int*)ei);
    k_cvt_edges<<<(N_EDGES + 255) / 256, 256>>>(ei);
    k_cvt_batch<<<(N_NODES + 255) / 256, 256>>>(batch);

    // CSR build + rank-2 layer-1 aggregation
    k_dinv<<<(N_NODES + 255) / 256, 256>>>();
    k_scan_block<<<NBLK, 256>>>();
    k_scan_top<<<1, 512>>>();
    k_scan_add<<<NBLK, 256>>>();
    k_scatter<<<(N_EDGES + 255) / 256, 256>>>(pos);
    k_selfq<<<NBLK, 256>>>(pos);

    // layer 1: analytic LN + fused expand
    k_stats1<<<1, 256>>>(w_conv1, b_conv1);
    k_expand<<<N_NODES, 256>>>(w_conv1, b_conv1, ln1_w, ln1_b, a1);

    // layer 2: tf32 GEMM + fp16 CSR aggregation
    k_gemm<<<dim3((N_NODES + 127) / 128, 4), 256>>>(w_conv2);
    k_agg2<<<(N_NODES * 32) / 256, 256>>>(b_conv2);
    k_stats2<<<1, 1>>>();

    // fused LN2 + PReLU + pooling, then MLP
    k_pool_ln<<<(N_NODES * 32 + 255) / 256, 256>>>(ln2_w, ln2_b, a2);
    k_pool_div<<<(N_GRAPHS * HID) / 256, 256>>>();
    k_lin1<<<(N_GRAPHS * MIDC) / 256, 256>>>(w_lin1, b_lin1);
    k_ln_mid<<<1, 1024>>>(lnm_w, lnm_b, am);
    k_lin2<<<(N_GRAPHS * OUTC) / 256, 256>>>(w_lin2, b_lin2, out);
}

// round 10
// speedup vs baseline: 4.3388x; 1.1290x over previous
#include <cuda_runtime.h>
#include <cuda_fp16.h>
#include <math.h>
#include <stdint.h>

#define N_NODES  100000
#define N_EDGES  3200000
#define N_GRAPHS 512
#define HID      256
#define MIDC     128
#define OUTC     16
#define LN_EPS   1e-5f
#define NBLK     391                    // ceil(N_NODES/256)

// ---------------- scratch (device globals) -----------------------------------
__device__ __align__(16) __half g_xh[(size_t)N_NODES * HID];   // layer-1 output (fp16)
__device__ __align__(16) __half g_hh[(size_t)N_NODES * HID];   // gemm output (fp16)
__device__ __align__(16) float  g_agg[(size_t)N_NODES * HID];  // layer-2 agg
__device__ float  g_dinv[N_NODES];
__device__ int    g_degi[N_NODES];
__device__ int    g_cur[N_NODES];
__device__ int    g_off[N_NODES + 1];
__device__ int    g_bsum[NBLK];
__device__ int    g_boff[NBLK];
__device__ int2   g_edge[N_EDGES];            // (src, nrm bits) sorted by dst
__device__ float  g_A[2 * N_NODES];           // rank-2 aggregate (layer 1)
__device__ double g_mA[5];                    // SA0,SA1,S00,S11,S01
__device__ float  g_stats1[2];                // mean, inv  (layer 1 LN)
__device__ double g_red[2];                   // sum, sumsq (layer 2 LN)
__device__ float  g_stats2[2];
__device__ __align__(16) float  g_pooled[N_GRAPHS * HID];
__device__ float  g_cnt[N_GRAPHS];
__device__ float  g_mid[N_GRAPHS * MIDC];
__device__ int    g_flag;                     // 1 = int32 input, 0 = int64
__device__ int    g_src[N_EDGES];
__device__ int    g_dst[N_EDGES];
__device__ int    g_batch[N_NODES];

// ---------------- helpers ----------------------------------------------------
__device__ __forceinline__ void red_add_v4(float4* p, float x, float y, float z, float w) {
    asm volatile("red.global.add.v4.f32 [%0], {%1,%2,%3,%4};"
                 :: "l"(p), "f"(x), "f"(y), "f"(z), "f"(w) : "memory");
}
__device__ __forceinline__ int clampi(int v, int hi) {
    return v < 0 ? 0 : (v >= hi ? hi - 1 : v);
}
__device__ __forceinline__ void mma_f16(float* c, const uint32_t* a, const uint32_t* b) {
    asm("mma.sync.aligned.m16n8k16.row.col.f32.f16.f16.f32 "
        "{%0,%1,%2,%3}, {%4,%5,%6,%7}, {%8,%9}, {%0,%1,%2,%3};"
        : "+f"(c[0]), "+f"(c[1]), "+f"(c[2]), "+f"(c[3])
        : "r"(a[0]), "r"(a[1]), "r"(a[2]), "r"(a[3]), "r"(b[0]), "r"(b[1]));
}

// ---------------- init / dtype / conversion ----------------------------------
__global__ void k_init() {
    int i = blockIdx.x * blockDim.x + threadIdx.x;
    if (i == 0) { g_flag = 0; g_red[0] = 0.0; g_red[1] = 0.0;
                  for (int k = 0; k < 5; k++) g_mA[k] = 0.0; }
    if (i < N_NODES) { g_degi[i] = 0; g_cur[i] = 0; }
    if (i < 2 * N_NODES) g_A[i] = 0.0f;
    if (i < N_GRAPHS * HID) g_pooled[i] = 0.0f;
    if (i < N_GRAPHS) g_cnt[i] = 0.0f;
}

__global__ void k_detect(const unsigned int* __restrict__ w) {
    int t = blockIdx.x * blockDim.x + threadIdx.x;         // 4096 threads
    long long idx = (long long)t * ((long long)N_EDGES / 4096);
    if (w[idx | 1] != 0u) atomicOr(&g_flag, 1);
}

// convert indices + degree histogram fused
__global__ void k_cvt_edges(const void* __restrict__ ei) {
    int e = blockIdx.x * blockDim.x + threadIdx.x;
    if (e >= N_EDGES) return;
    int s, d;
    if (g_flag) {
        const int* p = (const int*)ei;
        s = p[e]; d = p[N_EDGES + e];
    } else {
        const long long* p = (const long long*)ei;
        s = (int)p[e]; d = (int)p[N_EDGES + e];
    }
    s = clampi(s, N_NODES); d = clampi(d, N_NODES);
    g_src[e] = s;
    g_dst[e] = d;
    atomicAdd(&g_degi[d], 1);
}

__global__ void k_cvt_batch(const void* __restrict__ b) {
    int i = blockIdx.x * blockDim.x + threadIdx.x;
    if (i >= N_NODES) return;
    int v = g_flag ? ((const int*)b)[i] : (int)((const long long*)b)[i];
    g_batch[i] = clampi(v, N_GRAPHS);
}

// ---------------- CSR build ---------------------------------------------------
__global__ void k_dinv() {
    int i = blockIdx.x * blockDim.x + threadIdx.x;
    if (i < N_NODES) g_dinv[i] = rsqrtf((float)g_degi[i] + 1.0f);
}

__global__ void k_scan_block() {
    __shared__ int sh[256];
    int t = threadIdx.x, i = blockIdx.x * 256 + t;
    int v = (i < N_NODES) ? g_degi[i] : 0;
    sh[t] = v; __syncthreads();
    for (int o = 1; o < 256; o <<= 1) {
        int x = (t >= o) ? sh[t - o] : 0;
        __syncthreads(); sh[t] += x; __syncthreads();
    }
    if (i < N_NODES) g_off[i] = sh[t] - v;
    if (t == 255) g_bsum[blockIdx.x] = sh[255];
}

__global__ void k_scan_top() {
    __shared__ int sh[512];
    int t = threadIdx.x;
    int v = (t < NBLK) ? g_bsum[t] : 0;
    sh[t] = v; __syncthreads();
    for (int o = 1; o < 512; o <<= 1) {
        int x = (t >= o) ? sh[t - o] : 0;
        __syncthreads(); sh[t] += x; __syncthreads();
    }
    if (t < NBLK) g_boff[t] = sh[t] - v;
}

__global__ void k_scan_add() {
    int i = blockIdx.x * blockDim.x + threadIdx.x;
    if (i < N_NODES) g_off[i] += g_boff[i >> 8];
    if (i == 0) g_off[N_NODES] = N_EDGES;
}

// scatter edges by dst; fused rank-2 aggregation of pos for layer 1
__global__ void k_scatter(const float* __restrict__ pos) {
    int e = blockIdx.x * blockDim.x + threadIdx.x;
    if (e >= N_EDGES) return;
    int s = g_src[e], d = g_dst[e];
    float nrm = g_dinv[s] * g_dinv[d];
    int p = g_off[d] + atomicAdd(&g_cur[d], 1);
    g_edge[p] = make_int2(s, __float_as_int(nrm));
    atomicAdd(&g_A[2 * d + 0], nrm * pos[2 * s]);
    atomicAdd(&g_A[2 * d + 1], nrm * pos[2 * s + 1]);
}

// self-loop term + node-moment reduction (fused)
__global__ void k_selfq(const float* __restrict__ pos) {
    int n = blockIdx.x * blockDim.x + threadIdx.x;
    float a0 = 0.f, a1 = 0.f;
    if (n < N_NODES) {
        float d = g_dinv[n], d2 = d * d;
        a0 = g_A[2 * n + 0] + d2 * pos[2 * n];
        a1 = g_A[2 * n + 1] + d2 * pos[2 * n + 1];
        g_A[2 * n + 0] = a0;
        g_A[2 * n + 1] = a1;
    }
    __shared__ float sh[5][256];
    int t = threadIdx.x;
    sh[0][t] = a0; sh[1][t] = a1; sh[2][t] = a0 * a0; sh[3][t] = a1 * a1; sh[4][t] = a0 * a1;
    __syncthreads();
    for (int o = 128; o > 0; o >>= 1) {
        if (t < o)
            for (int k = 0; k < 5; k++) sh[k][t] += sh[k][t + o];
        __syncthreads();
    }
    if (t == 0)
        for (int k = 0; k < 5; k++) atomicAdd(&g_mA[k], (double)sh[k][0]);
}

// ---------------- layer 1: analytic LN stats + fused expand -------------------
__global__ void k_stats1(const float* __restrict__ w, const float* __restrict__ b) {
    __shared__ double sh[9][256];
    int c = threadIdx.x;
    double w0 = w[c], w1 = w[c + HID], bc = b[c];
    sh[0][c] = bc;        sh[1][c] = bc * bc;
    sh[2][c] = w0;        sh[3][c] = w1;
    sh[4][c] = w0 * w0;   sh[5][c] = w1 * w1;
    sh[6][c] = w0 * w1;   sh[7][c] = bc * w0;   sh[8][c] = bc * w1;
    __syncthreads();
    for (int o = 128; o > 0; o >>= 1) {
        if (c < o)
            for (int k = 0; k < 9; k++) sh[k][c] += sh[k][c + o];
        __syncthreads();
    }
    if (c == 0) {
        double Sb = sh[0][0], Sb2 = sh[1][0], SW0 = sh[2][0], SW1 = sh[3][0];
        double SW0q = sh[4][0], SW1q = sh[5][0], SW01 = sh[6][0];
        double SbW0 = sh[7][0], SbW1 = sh[8][0];
        double SA0 = g_mA[0], SA1 = g_mA[1], S00 = g_mA[2], S11 = g_mA[3], S01 = g_mA[4];
        double Nn = (double)N_NODES, NC = Nn * (double)HID;
        double sum = Nn * Sb + SA0 * SW0 + SA1 * SW1;
        double ss  = Nn * Sb2 + S00 * SW0q + S11 * SW1q
                   + 2.0 * (SA0 * SbW0 + SA1 * SbW1 + S01 * SW01);
        double mean = sum / NC;
        double var  = ss / NC - mean * mean;
        g_stats1[0] = (float)mean;
        g_stats1[1] = 1.0f / ((float)sqrt(var > 0.0 ? var : 0.0) + LN_EPS);
    }
}

// x1 = prelu(LN(b + A0*W0 + A1*W1))  -> fp16
__global__ void k_expand(const float* __restrict__ w, const float* __restrict__ b,
                         const float* __restrict__ lnw, const float* __restrict__ lnb,
                         const float* __restrict__ alpha) {
    int n = blockIdx.x, c = threadIdx.x;
    float A0 = g_A[2 * n], A1 = g_A[2 * n + 1];
    float pre = b[c] + A0 * w[c] + A1 * w[c + HID];
    float v = (pre - g_stats1[0]) * g_stats1[1] * lnw[c] + lnb[c];
    float a = *alpha;
    v = (v >= 0.0f) ? v : a * v;
    g_xh[(size_t)n * HID + c] = __float2half(v);
}

// ---------------- layer 2: fp16 tensor-core GEMM ------------------------------
// g_hh = g_xh (M x 256) @ W (256 x 256). Block 128x128, 8 warps of 32x64.
__global__ void k_gemm(const float* __restrict__ W) {
    __shared__ __half As[128][24];          // [m][k] 24-half stride: conflict-free frags
    __shared__ __half Bs[128][24];          // [n][k] transposed
    const int M = N_NODES;
    const int t = threadIdx.x;
    const int lane = t & 31, warp = t >> 5;
    const int wr = warp >> 1, wc = warp & 1;      // 4 row-warps x 2 col-warps
    const int g = lane >> 2, tig = lane & 3;
    const int bm = blockIdx.x * 128, bn = blockIdx.y * 128;

    float c[2][8][4];
    #pragma unroll
    for (int i = 0; i < 2; i++)
        #pragma unroll
        for (int j = 0; j < 8; j++)
            #pragma unroll
            for (int r = 0; r < 4; r++) c[i][j][r] = 0.0f;

    const int am = t >> 1, ak = (t & 1) * 8;      // A staging: row, 8-half offset
    const int bkk = t >> 4, bc = (t & 15) * 8;    // B staging: k-row, 8-col chunk

    for (int k0 = 0; k0 < 256; k0 += 16) {
        // stage A (fp16 direct)
        {
            int gr = bm + am;
            int4 v = make_int4(0, 0, 0, 0);
            if (gr < M) v = *(const int4*)(g_xh + (size_t)gr * 256 + k0 + ak);
            *(int4*)&As[am][ak] = v;
        }
        // stage B transposed: Bs[n][k] = (half)W[k][n]
        {
            const float4* p = (const float4*)(W + (size_t)(k0 + bkk) * 256 + bn + bc);
            float4 w0 = p[0], w1 = p[1];
            Bs[bc + 0][bkk] = __float2half(w0.x);
            Bs[bc + 1][bkk] = __float2half(w0.y);
            Bs[bc + 2][bkk] = __float2half(w0.z);
            Bs[bc + 3][bkk] = __float2half(w0.w);
            Bs[bc + 4][bkk] = __float2half(w1.x);
            Bs[bc + 5][bkk] = __float2half(w1.y);
            Bs[bc + 6][bkk] = __float2half(w1.z);
            Bs[bc + 7][bkk] = __float2half(w1.w);
        }
        __syncthreads();
        uint32_t a[2][4], b[8][2];
        #pragma unroll
        for (int i = 0; i < 2; i++) {
            int r0 = wr * 32 + i * 16 + g;
            a[i][0] = *(const uint32_t*)&As[r0][2 * tig];
            a[i][1] = *(const uint32_t*)&As[r0 + 8][2 * tig];
            a[i][2] = *(const uint32_t*)&As[r0][2 * tig + 8];
            a[i][3] = *(const uint32_t*)&As[r0 + 8][2 * tig + 8];
        }
        #pragma unroll
        for (int j = 0; j < 8; j++) {
            int cb = wc * 64 + j * 8 + g;
            b[j][0] = *(const uint32_t*)&Bs[cb][2 * tig];
            b[j][1] = *(const uint32_t*)&Bs[cb][2 * tig + 8];
        }
        #pragma unroll
        for (int i = 0; i < 2; i++)
            #pragma unroll
            for (int j = 0; j < 8; j++)
                mma_f16(c[i][j], a[i], b[j]);
        __syncthreads();
    }
    // epilogue: write fp16
    #pragma unroll
    for (int i = 0; i < 2; i++) {
        int r0 = bm + wr * 32 + i * 16 + g;
        int r1 = r0 + 8;
        #pragma unroll
        for (int j = 0; j < 8; j++) {
            int col = bn + wc * 64 + j * 8 + 2 * tig;
            if (r0 < M)
                *(__half2*)(g_hh + (size_t)r0 * 256 + col) = __floats2half2_rn(c[i][j][0], c[i][j][1]);
            if (r1 < M)
                *(__half2*)(g_hh + (size_t)r1 * 256 + col) = __floats2half2_rn(c[i][j][2], c[i][j][3]);
        }
    }
}

// warp-per-node CSR aggregation (fp16 gather, fp32 accum) + LN stats epilogue
__global__ void k_agg2(const float* __restrict__ bias) {
    int t = blockIdx.x * blockDim.x + threadIdx.x;
    int n = t >> 5;
    int lane = t & 31;
    float acc[8];
    {
        const float4* b4 = (const float4*)(bias + lane * 8);
        float4 x = b4[0], y = b4[1];
        acc[0] = x.x; acc[1] = x.y; acc[2] = x.z; acc[3] = x.w;
        acc[4] = y.x; acc[5] = y.y; acc[6] = y.z; acc[7] = y.w;
    }
    {
        float d = g_dinv[n], d2 = d * d;
        int4 v = ((const int4*)(g_hh + (size_t)n * HID))[lane];
        const __half2* h = (const __half2*)&v;
        #pragma unroll
        for (int i = 0; i < 4; i++) {
            float2 f = __half22float2(h[i]);
            acc[2 * i]     += d2 * f.x;
            acc[2 * i + 1] += d2 * f.y;
        }
    }
    int e = g_off[n], e1 = g_off[n + 1];
    for (; e + 1 < e1; e += 2) {
        int2 ea = g_edge[e], eb = g_edge[e + 1];
        float fa = __int_as_float(ea.y), fb = __int_as_float(eb.y);
        int4 va = ((const int4*)(g_hh + (size_t)ea.x * HID))[lane];
        int4 vb = ((const int4*)(g_hh + (size_t)eb.x * HID))[lane];
        const __half2* ha = (const __half2*)&va;
        const __half2* hb = (const __half2*)&vb;
        #pragma unroll
        for (int i = 0; i < 4; i++) {
            float2 xa = __half22float2(ha[i]);
            float2 xb = __half22float2(hb[i]);
            acc[2 * i]     += fa * xa.x + fb * xb.x;
            acc[2 * i + 1] += fa * xa.y + fb * xb.y;
        }
    }
    if (e < e1) {
        int2 ea = g_edge[e];
        float fa = __int_as_float(ea.y);
        int4 va = ((const int4*)(g_hh + (size_t)ea.x * HID))[lane];
        const __half2* ha = (const __half2*)&va;
        #pragma unroll
        for (int i = 0; i < 4; i++) {
            float2 xa = __half22float2(ha[i]);
            acc[2 * i]     += fa * xa.x;
            acc[2 * i + 1] += fa * xa.y;
        }
    }
    float4* out = (float4*)(g_agg + (size_t)n * HID);
    out[lane * 2]     = make_float4(acc[0], acc[1], acc[2], acc[3]);
    out[lane * 2 + 1] = make_float4(acc[4], acc[5], acc[6], acc[7]);
    float s = 0.f, s2 = 0.f;
    #pragma unroll
    for (int i = 0; i < 8; i++) { s += acc[i]; s2 += acc[i] * acc[i]; }
    for (int o = 16; o > 0; o >>= 1) {
        s  += __shfl_xor_sync(0xffffffffu, s,  o);
        s2 += __shfl_xor_sync(0xffffffffu, s2, o);
    }
    __shared__ float sh[2][8];
    int w = threadIdx.x >> 5;
    if (lane == 0) { sh[0][w] = s; sh[1][w] = s2; }
    __syncthreads();
    if (threadIdx.x == 0) {
        float ts = 0.f, ts2 = 0.f;
        #pragma unroll
        for (int i = 0; i < 8; i++) { ts += sh[0][i]; ts2 += sh[1][i]; }
        atomicAdd(&g_red[0], (double)ts);
        atomicAdd(&g_red[1], (double)ts2);
    }
}

__global__ void k_stats2() {
    double NC = (double)N_NODES * (double)HID;
    double mean = g_red[0] / NC;
    double var  = g_red[1] / NC - mean * mean;
    g_stats2[0] = (float)mean;
    g_stats2[1] = 1.0f / ((float)sqrt(var > 0.0 ? var : 0.0) + LN_EPS);
}

// fused LN2 + PReLU + mean-pool scatter
__global__ void k_pool_ln(const float* __restrict__ lnw, const float* __restrict__ lnb,
                          const float* __restrict__ alpha) {
    int t = blockIdx.x * blockDim.x + threadIdx.x;
    int n = t >> 5;
    if (n >= N_NODES) return;
    int lane = t & 31;
    float mean = g_stats2[0], inv = g_stats2[1], a = *alpha;
    const float4* x = (const float4*)(g_agg + (size_t)n * HID);
    const float4* w4 = (const float4*)lnw;
    const float4* b4 = (const float4*)lnb;
    float4* p = (float4*)(g_pooled + (size_t)g_batch[n] * HID);
    float4 v0 = x[lane], v1 = x[lane + 32];
    float4 w0 = w4[lane], w1 = w4[lane + 32];
    float4 c0 = b4[lane], c1 = b4[lane + 32];
    float r[8];
    r[0] = (v0.x - mean) * inv * w0.x + c0.x;
    r[1] = (v0.y - mean) * inv * w0.y + c0.y;
    r[2] = (v0.z - mean) * inv * w0.z + c0.z;
    r[3] = (v0.w - mean) * inv * w0.w + c0.w;
    r[4] = (v1.x - mean) * inv * w1.x + c1.x;
    r[5] = (v1.y - mean) * inv * w1.y + c1.y;
    r[6] = (v1.z - mean) * inv * w1.z + c1.z;
    r[7] = (v1.w - mean) * inv * w1.w + c1.w;
    #pragma unroll
    for (int i = 0; i < 8; i++) r[i] = (r[i] >= 0.0f) ? r[i] : a * r[i];
    red_add_v4(p + lane,      r[0], r[1], r[2], r[3]);
    red_add_v4(p + lane + 32, r[4], r[5], r[6], r[7]);
    if (lane == 0) atomicAdd(&g_cnt[g_batch[n]], 1.0f);
}

// ---------------- pooled MLP --------------------------------------------------
// mid = (pooled/cnt) @ w_lin1 + b  (pool-div folded into the dot product)
__global__ void k_lin1(const float* __restrict__ W, const float* __restrict__ bias) {
    int t = blockIdx.x * blockDim.x + threadIdx.x;   // 512*128
    int g = t >> 7, j = t & 127;
    const float* row = g_pooled + (size_t)g * HID;
    float s = 0.0f;
    #pragma unroll 8
    for (int c = 0; c < HID; c++) s += row[c] * W[(size_t)c * MIDC + j];
    g_mid[t] = s / fmaxf(g_cnt[g], 1.0f) + bias[j];
}

__global__ void k_ln_mid(const float* __restrict__ w, const float* __restrict__ b,
                         const float* __restrict__ alpha) {
    const int n = N_GRAPHS * MIDC;
    float a = *alpha;
    float s = 0.0f, s2 = 0.0f;
    for (int i = threadIdx.x; i < n; i += blockDim.x) {
        float v = g_mid[i]; s += v; s2 += v * v;
    }
    for (int o = 16; o > 0; o >>= 1) {
        s  += __shfl_xor_sync(0xffffffffu, s,  o);
        s2 += __shfl_xor_sync(0xffffffffu, s2, o);
    }
    __shared__ float sh[2][32];
    __shared__ float mstd[2];
    int wr = threadIdx.x >> 5, l = threadIdx.x & 31;
    if (l == 0) { sh[0][wr] = s; sh[1][wr] = s2; }
    __syncthreads();
    if (threadIdx.x == 0) {
        float ts = 0.0f, ts2 = 0.0f;
        int nw = blockDim.x >> 5;
        for (int i = 0; i < nw; i++) { ts += sh[0][i]; ts2 += sh[1][i]; }
        float mean = ts / n;
        float var  = ts2 / n - mean * mean;
        mstd[0] = mean;
        mstd[1] = 1.0f / (sqrtf(fmaxf(var, 0.0f)) + LN_EPS);
    }
    __syncthreads();
    float mean = mstd[0], inv = mstd[1];
    for (int i = threadIdx.x; i < n; i += blockDim.x) {
        int c = i & (MIDC - 1);
        float v = (g_mid[i] - mean) * inv * w[c] + b[c];
        g_mid[i] = (v >= 0.0f) ? v : a * v;
    }
}

__global__ void k_lin2(const float* __restrict__ W, const float* __restrict__ bias,
                       float* __restrict__ out) {
    int t = blockIdx.x * blockDim.x + threadIdx.x;   // 512*16
    int g = t >> 4, o = t & 15;
    const float* row = g_mid + (size_t)g * MIDC;
    float s = 0.0f;
    #pragma unroll 8
    for (int j = 0; j < MIDC; j++) s += row[j] * W[(size_t)j * OUTC + o];
    out[t] = s + bias[o];
}

// ---------------- launch -----------------------------------------------------
extern "C" void kernel_launch(void* const* d_in, const int* in_sizes, int n_in,
                              void* d_out, int out_size) {
    const float* pos    = (const float*)d_in[0];
    const void*  ei     = d_in[1];
    const void*  batch  = d_in[2];
    const float* w_conv1 = (const float*)d_in[3];
    const float* b_conv1 = (const float*)d_in[4];
    const float* ln1_w   = (const float*)d_in[5];
    const float* ln1_b   = (const float*)d_in[6];
    const float* a1      = (const float*)d_in[7];
    const float* w_conv2 = (const float*)d_in[8];
    const float* b_conv2 = (const float*)d_in[9];
    const float* ln2_w   = (const float*)d_in[10];
    const float* ln2_b   = (const float*)d_in[11];
    const float* a2      = (const float*)d_in[12];
    const float* w_lin1  = (const float*)d_in[13];
    const float* b_lin1  = (const float*)d_in[14];
    const float* lnm_w   = (const float*)d_in[15];
    const float* lnm_b   = (const float*)d_in[16];
    const float* am      = (const float*)d_in[17];
    const float* w_lin2  = (const float*)d_in[18];
    const float* b_lin2  = (const float*)d_in[19];
    float* out = (float*)d_out;

    // init + dtype detect + index conversion (+degree hist fused)
    k_init<<<(2 * N_NODES + 255) / 256, 256>>>();
    k_detect<<<16, 256>>>((const unsigned int*)ei);
    k_cvt_edges<<<(N_EDGES + 255) / 256, 256>>>(ei);
    k_cvt_batch<<<(N_NODES + 255) / 256, 256>>>(batch);

    // CSR build + rank-2 layer-1 aggregation
    k_dinv<<<(N_NODES + 255) / 256, 256>>>();
    k_scan_block<<<NBLK, 256>>>();
    k_scan_top<<<1, 512>>>();
    k_scan_add<<<NBLK, 256>>>();
    k_scatter<<<(N_EDGES + 255) / 256, 256>>>(pos);
    k_selfq<<<NBLK, 256>>>(pos);

    // layer 1: analytic LN + fused expand (fp16 out)
    k_stats1<<<1, 256>>>(w_conv1, b_conv1);
    k_expand<<<N_NODES, 256>>>(w_conv1, b_conv1, ln1_w, ln1_b, a1);

    // layer 2: fp16 tensor-core GEMM + fp16 CSR aggregation
    k_gemm<<<dim3((N_NODES + 127) / 128, 2), 256>>>(w_conv2);
    k_agg2<<<(N_NODES * 32) / 256, 256>>>(b_conv2);
    k_stats2<<<1, 1>>>();

    // fused LN2 + PReLU + pooling, then MLP (pool-div folded into lin1)
    k_pool_ln<<<(N_NODES * 32 + 255) / 256, 256>>>(ln2_w, ln2_b, a2);
    k_lin1<<<(N_GRAPHS * MIDC) / 256, 256>>>(w_lin1, b_lin1);
    k_ln_mid<<<1, 1024>>>(lnm_w, lnm_b, am);
    k_lin2<<<(N_GRAPHS * OUTC) / 256, 256>>>(w_lin2, b_lin2, out);
}

// round 12
// speedup vs baseline: 4.6358x; 1.0685x over previous
#include <cuda_runtime.h>
#include <cuda_fp16.h>
#include <math.h>
#include <stdint.h>

#define N_NODES  100000
#define N_EDGES  3200000
#define N_GRAPHS 512
#define HID      256
#define MIDC     128
#define OUTC     16
#define LN_EPS   1e-5f
#define NBLK     391                    // ceil(N_NODES/256)

// ---------------- scratch (device globals) -----------------------------------
__device__ __align__(16) __half g_hh[(size_t)N_NODES * HID];   // gemm output (fp16)
__device__ __align__(16) __half g_agg[(size_t)N_NODES * HID];  // layer-2 agg (fp16)
__device__ float  g_dinv[N_NODES];
__device__ int    g_degi[N_NODES];
__device__ int    g_cur[N_NODES];
__device__ int    g_off[N_NODES + 1];
__device__ int    g_bsum[NBLK];
__device__ int    g_boff[NBLK];
__device__ int    g_esrc[N_EDGES];            // src ids, sorted by dst
__device__ float  g_A[2 * N_NODES];           // rank-2 aggregate (layer 1)
__device__ double g_mA[5];                    // SA0,SA1,S00,S11,S01
__device__ __align__(16) float g_c0[HID];     // fused layer-1 affine constants
__device__ __align__(16) float g_c1[HID];
__device__ __align__(16) float g_c2[HID];
__device__ double g_red[2];                   // sum, sumsq (layer 2 LN)
__device__ __align__(16) float  g_pooled[N_GRAPHS * HID];
__device__ float  g_cnt[N_GRAPHS];
__device__ float  g_mid[N_GRAPHS * MIDC];
__device__ int    g_flag;                     // 1 = int32 input, 0 = int64
__device__ int    g_batch[N_NODES];

// ---------------- helpers ----------------------------------------------------
__device__ __forceinline__ void red_add_v4(float4* p, float x, float y, float z, float w) {
    asm volatile("red.global.add.v4.f32 [%0], {%1,%2,%3,%4};"
                 :: "l"(p), "f"(x), "f"(y), "f"(z), "f"(w) : "memory");
}
__device__ __forceinline__ int clampi(int v, int hi) {
    return v < 0 ? 0 : (v >= hi ? hi - 1 : v);
}
__device__ __forceinline__ void mma_f16(float* c, const uint32_t* a, const uint32_t* b) {
    asm("mma.sync.aligned.m16n8k16.row.col.f32.f16.f16.f32 "
        "{%0,%1,%2,%3}, {%4,%5,%6,%7}, {%8,%9}, {%0,%1,%2,%3};"
        : "+f"(c[0]), "+f"(c[1]), "+f"(c[2]), "+f"(c[3])
        : "r"(a[0]), "r"(a[1]), "r"(a[2]), "r"(a[3]), "r"(b[0]), "r"(b[1]));
}

// ---------------- init / dtype / conversion ----------------------------------
__global__ void k_init() {
    int i = blockIdx.x * blockDim.x + threadIdx.x;
    if (i == 0) { g_flag = 0; g_red[0] = 0.0; g_red[1] = 0.0;
                  for (int k = 0; k < 5; k++) g_mA[k] = 0.0; }
    if (i < N_NODES) { g_degi[i] = 0; g_cur[i] = 0; }
    if (i < 2 * N_NODES) g_A[i] = 0.0f;
    if (i < N_GRAPHS * HID) g_pooled[i] = 0.0f;
    if (i < N_GRAPHS) g_cnt[i] = 0.0f;
}

__global__ void k_detect(const unsigned int* __restrict__ w) {
    int t = blockIdx.x * blockDim.x + threadIdx.x;         // 4096 threads
    long long idx = (long long)t * ((long long)N_EDGES / 4096);
    if (w[idx | 1] != 0u) atomicOr(&g_flag, 1);
}

// degree histogram (decodes dst only)
__global__ void k_hist(const void* __restrict__ ei) {
    int e = blockIdx.x * blockDim.x + threadIdx.x;
    if (e >= N_EDGES) return;
    int d = g_flag ? ((const int*)ei)[N_EDGES + e]
                   : (int)((const long long*)ei)[N_EDGES + e];
    atomicAdd(&g_degi[clampi(d, N_NODES)], 1);
}

__global__ void k_cvt_batch(const void* __restrict__ b) {
    int i = blockIdx.x * blockDim.x + threadIdx.x;
    if (i >= N_NODES) return;
    int v = g_flag ? ((const int*)b)[i] : (int)((const long long*)b)[i];
    g_batch[i] = clampi(v, N_GRAPHS);
}

// ---------------- CSR build (dinv fused into block scan) ----------------------
__global__ void k_scan_block() {
    __shared__ int sh[256];
    int t = threadIdx.x, i = blockIdx.x * 256 + t;
    int v = (i < N_NODES) ? g_degi[i] : 0;
    sh[t] = v; __syncthreads();
    for (int o = 1; o < 256; o <<= 1) {
        int x = (t >= o) ? sh[t - o] : 0;
        __syncthreads(); sh[t] += x; __syncthreads();
    }
    if (i < N_NODES) {
        g_off[i]  = sh[t] - v;
        g_dinv[i] = rsqrtf((float)v + 1.0f);     // +1: self loop
    }
    if (t == 255) g_bsum[blockIdx.x] = sh[255];
}

__global__ void k_scan_top() {
    __shared__ int sh[512];
    int t = threadIdx.x;
    int v = (t < NBLK) ? g_bsum[t] : 0;
    sh[t] = v; __syncthreads();
    for (int o = 1; o < 512; o <<= 1) {
        int x = (t >= o) ? sh[t - o] : 0;
        __syncthreads(); sh[t] += x; __syncthreads();
    }
    if (t < NBLK) g_boff[t] = sh[t] - v;
}

__global__ void k_scan_add() {
    int i = blockIdx.x * blockDim.x + threadIdx.x;
    if (i < N_NODES) g_off[i] += g_boff[i >> 8];
    if (i == 0) g_off[N_NODES] = N_EDGES;
}

// scatter edges (src only) by dst; fused rank-2 aggregation of pos for layer 1
__global__ void k_scatter(const void* __restrict__ ei, const float* __restrict__ pos) {
    int e = blockIdx.x * blockDim.x + threadIdx.x;
    if (e >= N_EDGES) return;
    int s, d;
    if (g_flag) {
        const int* p = (const int*)ei;
        s = p[e]; d = p[N_EDGES + e];
    } else {
        const long long* p = (const long long*)ei;
        s = (int)p[e]; d = (int)p[N_EDGES + e];
    }
    s = clampi(s, N_NODES); d = clampi(d, N_NODES);
    float nrm = g_dinv[s] * g_dinv[d];
    int p = g_off[d] + atomicAdd(&g_cur[d], 1);
    g_esrc[p] = s;
    atomicAdd(&g_A[2 * d + 0], nrm * pos[2 * s]);
    atomicAdd(&g_A[2 * d + 1], nrm * pos[2 * s + 1]);
}

// self-loop term + node-moment reduction (fused)
__global__ void k_selfq(const float* __restrict__ pos) {
    int n = blockIdx.x * blockDim.x + threadIdx.x;
    float a0 = 0.f, a1 = 0.f;
    if (n < N_NODES) {
        float d = g_dinv[n], d2 = d * d;
        a0 = g_A[2 * n + 0] + d2 * pos[2 * n];
        a1 = g_A[2 * n + 1] + d2 * pos[2 * n + 1];
        g_A[2 * n + 0] = a0;
        g_A[2 * n + 1] = a1;
    }
    __shared__ float sh[5][256];
    int t = threadIdx.x;
    sh[0][t] = a0; sh[1][t] = a1; sh[2][t] = a0 * a0; sh[3][t] = a1 * a1; sh[4][t] = a0 * a1;
    __syncthreads();
    for (int o = 128; o > 0; o >>= 1) {
        if (t < o)
            for (int k = 0; k < 5; k++) sh[k][t] += sh[k][t + o];
        __syncthreads();
    }
    if (t == 0)
        for (int k = 0; k < 5; k++) atomicAdd(&g_mA[k], (double)sh[k][0]);
}

// ---------------- layer 1: analytic LN stats + fused affine constants --------
// After stats, writes c0/c1/c2 so that x1 = prelu(c0 + A0*c1 + A1*c2).
__global__ void k_stats1(const float* __restrict__ w, const float* __restrict__ b,
                         const float* __restrict__ lnw, const float* __restrict__ lnb) {
    __shared__ double sh[9][256];
    __shared__ float mstd[2];
    int c = threadIdx.x;
    double w0 = w[c], w1 = w[c + HID], bc = b[c];
    sh[0][c] = bc;        sh[1][c] = bc * bc;
    sh[2][c] = w0;        sh[3][c] = w1;
    sh[4][c] = w0 * w0;   sh[5][c] = w1 * w1;
    sh[6][c] = w0 * w1;   sh[7][c] = bc * w0;   sh[8][c] = bc * w1;
    __syncthreads();
    for (int o = 128; o > 0; o >>= 1) {
        if (c < o)
            for (int k = 0; k < 9; k++) sh[k][c] += sh[k][c + o];
        __syncthreads();
    }
    if (c == 0) {
        double Sb = sh[0][0], Sb2 = sh[1][0], SW0 = sh[2][0], SW1 = sh[3][0];
        double SW0q = sh[4][0], SW1q = sh[5][0], SW01 = sh[6][0];
        double SbW0 = sh[7][0], SbW1 = sh[8][0];
        double SA0 = g_mA[0], SA1 = g_mA[1], S00 = g_mA[2], S11 = g_mA[3], S01 = g_mA[4];
        double Nn = (double)N_NODES, NC = Nn * (double)HID;
        double sum = Nn * Sb + SA0 * SW0 + SA1 * SW1;
        double ss  = Nn * Sb2 + S00 * SW0q + S11 * SW1q
                   + 2.0 * (SA0 * SbW0 + SA1 * SbW1 + S01 * SW01);
        double mean = sum / NC;
        double var  = ss / NC - mean * mean;
        mstd[0] = (float)mean;
        mstd[1] = 1.0f / ((float)sqrt(var > 0.0 ? var : 0.0) + LN_EPS);
    }
    __syncthreads();
    float mean = mstd[0], inv = mstd[1];
    float lw = lnw[c], lb = lnb[c];
    g_c0[c] = ((float)b[c] - mean) * inv * lw + lb;
    g_c1[c] = (float)w[c]       * inv * lw;
    g_c2[c] = (float)w[c + HID] * inv * lw;
}

// ---------------- layer 2: fp16 tensor-core GEMM with fused A generation -----
// A[m][k] = prelu(c0[k] + A0(m)*c1[k] + A1(m)*c2[k]);  g_hh = A @ W.
__global__ void k_gemm(const float* __restrict__ W, const float* __restrict__ alpha) {
    __shared__ __half As[128][24];
    __shared__ __half Bs[128][24];
    const int M = N_NODES;
    const int t = threadIdx.x;
    const int lane = t & 31, warp = t >> 5;
    const int wr = warp >> 1, wc = warp & 1;
    const int g = lane >> 2, tig = lane & 3;
    const int bm = blockIdx.x * 128, bn = blockIdx.y * 128;

    float c[2][8][4];
    #pragma unroll
    for (int i = 0; i < 2; i++)
        #pragma unroll
        for (int j = 0; j < 8; j++)
            #pragma unroll
            for (int r = 0; r < 4; r++) c[i][j][r] = 0.0f;

    const int am = t >> 1, ak = (t & 1) * 8;
    const int bkk = t >> 4, bc = (t & 15) * 8;

    // per-thread row state for A generation (row fixed across k-iters)
    const int gr = bm + am;
    float A0 = 0.f, A1 = 0.f;
    if (gr < M) { A0 = g_A[2 * gr]; A1 = g_A[2 * gr + 1]; }
    const float pa = *alpha;

    for (int k0 = 0; k0 < 256; k0 += 16) {
        // stage A: generate 8 channels from affine constants + prelu
        {
            const float4* C0 = (const float4*)(g_c0 + k0 + ak);
            const float4* C1 = (const float4*)(g_c1 + k0 + ak);
            const float4* C2 = (const float4*)(g_c2 + k0 + ak);
            float v[8];
            float4 x0 = C0[0], x1 = C0[1];
            float4 y0 = C1[0], y1 = C1[1];
            float4 z0 = C2[0], z1 = C2[1];
            v[0] = x0.x + A0 * y0.x + A1 * z0.x;
            v[1] = x0.y + A0 * y0.y + A1 * z0.y;
            v[2] = x0.z + A0 * y0.z + A1 * z0.z;
            v[3] = x0.w + A0 * y0.w + A1 * z0.w;
            v[4] = x1.x + A0 * y1.x + A1 * z1.x;
            v[5] = x1.y + A0 * y1.y + A1 * z1.y;
            v[6] = x1.z + A0 * y1.z + A1 * z1.z;
            v[7] = x1.w + A0 * y1.w + A1 * z1.w;
            #pragma unroll
            for (int i = 0; i < 8; i++) v[i] = (v[i] >= 0.f) ? v[i] : pa * v[i];
            __half2 h[4];
            #pragma unroll
            for (int i = 0; i < 4; i++) h[i] = __floats2half2_rn(v[2 * i], v[2 * i + 1]);
            *(int4*)&As[am][ak] = *(const int4*)h;
        }
        // stage B transposed: Bs[n][k] = (half)W[k][n]
        {
            const float4* p = (const float4*)(W + (size_t)(k0 + bkk) * 256 + bn + bc);
            float4 w0 = p[0], w1 = p[1];
            Bs[bc + 0][bkk] = __float2half(w0.x);
            Bs[bc + 1][bkk] = __float2half(w0.y);
            Bs[bc + 2][bkk] = __float2half(w0.z);
            Bs[bc + 3][bkk] = __float2half(w0.w);
            Bs[bc + 4][bkk] = __float2half(w1.x);
            Bs[bc + 5][bkk] = __float2half(w1.y);
            Bs[bc + 6][bkk] = __float2half(w1.z);
            Bs[bc + 7][bkk] = __float2half(w1.w);
        }
        __syncthreads();
        uint32_t a[2][4], b[8][2];
        #pragma unroll
        for (int i = 0; i < 2; i++) {
            int r0 = wr * 32 + i * 16 + g;
            a[i][0] = *(const uint32_t*)&As[r0][2 * tig];
            a[i][1] = *(const uint32_t*)&As[r0 + 8][2 * tig];
            a[i][2] = *(const uint32_t*)&As[r0][2 * tig + 8];
            a[i][3] = *(const uint32_t*)&As[r0 + 8][2 * tig + 8];
        }
        #pragma unroll
        for (int j = 0; j < 8; j++) {
            int cb = wc * 64 + j * 8 + g;
            b[j][0] = *(const uint32_t*)&Bs[cb][2 * tig];
            b[j][1] = *(const uint32_t*)&Bs[cb][2 * tig + 8];
        }
        #pragma unroll
        for (int i = 0; i < 2; i++)
            #pragma unroll
            for (int j = 0; j < 8; j++)
                mma_f16(c[i][j], a[i], b[j]);
        __syncthreads();
    }
    #pragma unroll
    for (int i = 0; i < 2; i++) {
        int r0 = bm + wr * 32 + i * 16 + g;
        int r1 = r0 + 8;
        #pragma unroll
        for (int j = 0; j < 8; j++) {
            int col = bn + wc * 64 + j * 8 + 2 * tig;
            if (r0 < M)
                *(__half2*)(g_hh + (size_t)r0 * 256 + col) = __floats2half2_rn(c[i][j][0], c[i][j][1]);
            if (r1 < M)
                *(__half2*)(g_hh + (size_t)r1 * 256 + col) = __floats2half2_rn(c[i][j][2], c[i][j][3]);
        }
    }
}

// warp-per-node CSR aggregation (fp16 gather, fp32 accum, fp16 out) + LN stats
__global__ void k_agg2(const float* __restrict__ bias) {
    int t = blockIdx.x * blockDim.x + threadIdx.x;
    int n = t >> 5;
    int lane = t & 31;
    float dn = g_dinv[n];
    float acc[8];
    {
        const float4* b4 = (const float4*)(bias + lane * 8);
        float4 x = b4[0], y = b4[1];
        acc[0] = x.x; acc[1] = x.y; acc[2] = x.z; acc[3] = x.w;
        acc[4] = y.x; acc[5] = y.y; acc[6] = y.z; acc[7] = y.w;
    }
    {
        float d2 = dn * dn;
        int4 v = ((const int4*)(g_hh + (size_t)n * HID))[lane];
        const __half2* h = (const __half2*)&v;
        #pragma unroll
        for (int i = 0; i < 4; i++) {
            float2 f = __half22float2(h[i]);
            acc[2 * i]     += d2 * f.x;
            acc[2 * i + 1] += d2 * f.y;
        }
    }
    int e = g_off[n], e1 = g_off[n + 1];
    for (; e + 1 < e1; e += 2) {
        int sa = g_esrc[e], sb = g_esrc[e + 1];
        float fa = g_dinv[sa] * dn, fb = g_dinv[sb] * dn;
        int4 va = ((const int4*)(g_hh + (size_t)sa * HID))[lane];
        int4 vb = ((const int4*)(g_hh + (size_t)sb * HID))[lane];
        const __half2* ha = (const __half2*)&va;
        const __half2* hb = (const __half2*)&vb;
        #pragma unroll
        for (int i = 0; i < 4; i++) {
            float2 xa = __half22float2(ha[i]);
            float2 xb = __half22float2(hb[i]);
            acc[2 * i]     += fa * xa.x + fb * xb.x;
            acc[2 * i + 1] += fa * xa.y + fb * xb.y;
        }
    }
    if (e < e1) {
        int sa = g_esrc[e];
        float fa = g_dinv[sa] * dn;
        int4 va = ((const int4*)(g_hh + (size_t)sa * HID))[lane];
        const __half2* ha = (const __half2*)&va;
        #pragma unroll
        for (int i = 0; i < 4; i++) {
            float2 xa = __half22float2(ha[i]);
            acc[2 * i]     += fa * xa.x;
            acc[2 * i + 1] += fa * xa.y;
        }
    }
    {   // write agg as fp16
        __half2 h[4];
        #pragma unroll
        for (int i = 0; i < 4; i++) h[i] = __floats2half2_rn(acc[2 * i], acc[2 * i + 1]);
        ((int4*)(g_agg + (size_t)n * HID))[lane] = *(const int4*)h;
    }
    float s = 0.f, s2 = 0.f;
    #pragma unroll
    for (int i = 0; i < 8; i++) { s += acc[i]; s2 += acc[i] * acc[i]; }
    for (int o = 16; o > 0; o >>= 1) {
        s  += __shfl_xor_sync(0xffffffffu, s,  o);
        s2 += __shfl_xor_sync(0xffffffffu, s2, o);
    }
    __shared__ float sh[2][8];
    int w = threadIdx.x >> 5;
    if (lane == 0) { sh[0][w] = s; sh[1][w] = s2; }
    __syncthreads();
    if (threadIdx.x == 0) {
        float ts = 0.f, ts2 = 0.f;
        #pragma unroll
        for (int i = 0; i < 8; i++) { ts += sh[0][i]; ts2 += sh[1][i]; }
        atomicAdd(&g_red[0], (double)ts);
        atomicAdd(&g_red[1], (double)ts2);
    }
}

// fused LN2 + PReLU + mean-pool scatter (stats derived inline from g_red)
__global__ void k_pool_ln(const float* __restrict__ lnw, const float* __restrict__ lnb,
                          const float* __restrict__ alpha) {
    int t = blockIdx.x * blockDim.x + threadIdx.x;
    int n = t >> 5;
    if (n >= N_NODES) return;
    int lane = t & 31;
    double NC = (double)N_NODES * (double)HID;
    double mean_d = g_red[0] / NC;
    double var_d  = g_red[1] / NC - mean_d * mean_d;
    float mean = (float)mean_d;
    float inv  = 1.0f / ((float)sqrt(var_d > 0.0 ? var_d : 0.0) + LN_EPS);
    float a = *alpha;
    int4 v = ((const int4*)(g_agg + (size_t)n * HID))[lane];
    const __half2* h = (const __half2*)&v;
    const float4* w4 = (const float4*)(lnw + lane * 8);
    const float4* b4 = (const float4*)(lnb + lane * 8);
    float4 w0 = w4[0], w1 = w4[1];
    float4 c0 = b4[0], c1 = b4[1];
    float x[8];
    #pragma unroll
    for (int i = 0; i < 4; i++) {
        float2 f = __half22float2(h[i]);
        x[2 * i] = f.x; x[2 * i + 1] = f.y;
    }
    float r[8];
    r[0] = (x[0] - mean) * inv * w0.x + c0.x;
    r[1] = (x[1] - mean) * inv * w0.y + c0.y;
    r[2] = (x[2] - mean) * inv * w0.z + c0.z;
    r[3] = (x[3] - mean) * inv * w0.w + c0.w;
    r[4] = (x[4] - mean) * inv * w1.x + c1.x;
    r[5] = (x[5] - mean) * inv * w1.y + c1.y;
    r[6] = (x[6] - mean) * inv * w1.z + c1.z;
    r[7] = (x[7] - mean) * inv * w1.w + c1.w;
    #pragma unroll
    for (int i = 0; i < 8; i++) r[i] = (r[i] >= 0.0f) ? r[i] : a * r[i];
    float4* p = (float4*)(g_pooled + (size_t)g_batch[n] * HID + lane * 8);
    red_add_v4(p,     r[0], r[1], r[2], r[3]);
    red_add_v4(p + 1, r[4], r[5], r[6], r[7]);
    if (lane == 0) atomicAdd(&g_cnt[g_batch[n]], 1.0f);
}

// ---------------- pooled MLP --------------------------------------------------
__global__ void k_lin1(const float* __restrict__ W, const float* __restrict__ bias) {
    int t = blockIdx.x * blockDim.x + threadIdx.x;   // 512*128
    int g = t >> 7, j = t & 127;
    const float* row = g_pooled + (size_t)g * HID;
    float s = 0.0f;
    #pragma unroll 8
    for (int c = 0; c < HID; c++) s += row[c] * W[(size_t)c * MIDC + j];
    g_mid[t] = s / fmaxf(g_cnt[g], 1.0f) + bias[j];
}

__global__ void k_ln_mid(const float* __restrict__ w, const float* __restrict__ b,
                         const float* __restrict__ alpha) {
    const int n = N_GRAPHS * MIDC;
    float a = *alpha;
    float s = 0.0f, s2 = 0.0f;
    for (int i = threadIdx.x; i < n; i += blockDim.x) {
        float v = g_mid[i]; s += v; s2 += v * v;
    }
    for (int o = 16; o > 0; o >>= 1) {
        s  += __shfl_xor_sync(0xffffffffu, s,  o);
        s2 += __shfl_xor_sync(0xffffffffu, s2, o);
    }
    __shared__ float sh[2][32];
    __shared__ float mstd[2];
    int wr = threadIdx.x >> 5, l = threadIdx.x & 31;
    if (l == 0) { sh[0][wr] = s; sh[1][wr] = s2; }
    __syncthreads();
    if (threadIdx.x == 0) {
        float ts = 0.0f, ts2 = 0.0f;
        int nw = blockDim.x >> 5;
        for (int i = 0; i < nw; i++) { ts += sh[0][i]; ts2 += sh[1][i]; }
        float mean = ts / n;
        float var  = ts2 / n - mean * mean;
        mstd[0] = mean;
        mstd[1] = 1.0f / (sqrtf(fmaxf(var, 0.0f)) + LN_EPS);
    }
    __syncthreads();
    float mean = mstd[0], inv = mstd[1];
    for (int i = threadIdx.x; i < n; i += blockDim.x) {
        int c = i & (MIDC - 1);
        float v = (g_mid[i] - mean) * inv * w[c] + b[c];
        g_mid[i] = (v >= 0.0f) ? v : a * v;
    }
}

__global__ void k_lin2(const float* __restrict__ W, const float* __restrict__ bias,
                       float* __restrict__ out) {
    int t = blockIdx.x * blockDim.x + threadIdx.x;   // 512*16
    int g = t >> 4, o = t & 15;
    const float* row = g_mid + (size_t)g * MIDC;
    float s = 0.0f;
    #pragma unroll 8
    for (int j = 0; j < MIDC; j++) s += row[j] * W[(size_t)j * OUTC + o];
    out[t] = s + bias[o];
}

// ---------------- launch -----------------------------------------------------
extern "C" void kernel_launch(void* const* d_in, const int* in_sizes, int n_in,
                              void* d_out, int out_size) {
    const float* pos    = (const float*)d_in[0];
    const void*  ei     = d_in[1];
    const void*  batch  = d_in[2];
    const float* w_conv1 = (const float*)d_in[3];
    const float* b_conv1 = (const float*)d_in[4];
    const float* ln1_w   = (const float*)d_in[5];
    const float* ln1_b   = (const float*)d_in[6];
    const float* a1      = (const float*)d_in[7];
    const float* w_conv2 = (const float*)d_in[8];
    const float* b_conv2 = (const float*)d_in[9];
    const float* ln2_w   = (const float*)d_in[10];
    const float* ln2_b   = (const float*)d_in[11];
    const float* a2      = (const float*)d_in[12];
    const float* w_lin1  = (const float*)d_in[13];
    const float* b_lin1  = (const float*)d_in[14];
    const float* lnm_w   = (const float*)d_in[15];
    const float* lnm_b   = (const float*)d_in[16];
    const float* am      = (const float*)d_in[17];
    const float* w_lin2  = (const float*)d_in[18];
    const float* b_lin2  = (const float*)d_in[19];
    float* out = (float*)d_out;

    // init + dtype detect + histogram + batch conversion
    k_init<<<(2 * N_NODES + 255) / 256, 256>>>();
    k_detect<<<16, 256>>>((const unsigned int*)ei);
    k_hist<<<(N_EDGES + 255) / 256, 256>>>(ei);
    k_cvt_batch<<<(N_NODES + 255) / 256, 256>>>(batch);

    // CSR build (dinv fused into scan) + rank-2 layer-1 aggregation
    k_scan_block<<<NBLK, 256>>>();
    k_scan_top<<<1, 512>>>();
    k_scan_add<<<NBLK, 256>>>();
    k_scatter<<<(N_EDGES + 255) / 256, 256>>>(ei, pos);
    k_selfq<<<NBLK, 256>>>(pos);

    // layer 1: analytic LN stats -> fused affine constants
    k_stats1<<<1, 256>>>(w_conv1, b_conv1, ln1_w, ln1_b);

    // layer 2: GEMM with fused A generation, then fp16 CSR aggregation
    k_gemm<<<dim3((N_NODES + 127) / 128, 2), 256>>>(w_conv2, a1);
    k_agg2<<<(N_NODES * 32) / 256, 256>>>(b_conv2);

    // fused LN2 + PReLU + pooling, then MLP
    k_pool_ln<<<(N_NODES * 32 + 255) / 256, 256>>>(ln2_w, ln2_b, a2);
    k_lin1<<<(N_GRAPHS * MIDC) / 256, 256>>>(w_lin1, b_lin1);
    k_ln_mid<<<1, 1024>>>(lnm_w, lnm_b, am);
    k_lin2<<<(N_GRAPHS * OUTC) / 256, 256>>>(w_lin2, b_lin2, out);
}